// round 10
// baseline (speedup 1.0000x reference)
#include <cuda_runtime.h>
#include <cuda_bf16.h>
#include <cstdint>
#include <math.h>

#define NNODES 100000
#define NEDGES 1600000
#define SCAN_BS 256
#define BKP 40
#define ARR (128 * BKP)          // bf16 elems per smem array
#define GEMM_SMEM (2 * 4 * ARR * 2)   // 2 stages x 4 arrays x bf16 = 81920 B

// ---------------------------------------------------------------------------
// Scratch (device globals; allocation-free per harness rules)
// ---------------------------------------------------------------------------
__device__ float g_dis[NNODES];
__device__ float g_xw[(size_t)NNODES * 128];     // fp32 gather source (dual gemm out)
__device__ float g_agg[(size_t)NNODES * 128];    // clsf agg buffer (fp32)
__device__ float g_agg2[(size_t)NNODES * 128];   // enc agg buffer (fp32)
// bf16 hi/lo activation pairs
__device__ __nv_bfloat16 g_pAhi[(size_t)NNODES * 256], g_pAlo[(size_t)NNODES * 256]; // relu(h0c)
__device__ __nv_bfloat16 g_pBhi[(size_t)NNODES * 128], g_pBlo[(size_t)NNODES * 128];
__device__ __nv_bfloat16 g_pChi[(size_t)NNODES * 128], g_pClo[(size_t)NNODES * 128];
__device__ __nv_bfloat16 g_pDhi[(size_t)NNODES * 128], g_pDlo[(size_t)NNODES * 128]; // aggx
__device__ int   g_rows[NEDGES];
__device__ int   g_cols[NEDGES];
__device__ int   g_cnt[NNODES];
__device__ int   g_cur[NNODES];
__device__ int   g_rowptr[NNODES + 1];
__device__ int   g_btot[(NNODES + SCAN_BS - 1) / SCAN_BS + 1];
__device__ int   g_boff[(NNODES + SCAN_BS - 1) / SCAN_BS + 1];
__device__ int   g_csr_src[NEDGES];
__device__ float g_csr_norm[NEDGES];
__device__ int   g_is64;
// pre-converted weights, [n][k] layout, bf16 hi/lo
__device__ __nv_bfloat16 g_whi[131072];
__device__ __nv_bfloat16 g_wlo[131072];

// ---------------------------------------------------------------------------
// Preprocessing
// ---------------------------------------------------------------------------
__global__ void detect_dtype_kernel(const void* ei_raw, int N) {
    const long long* p = (const long long*)ei_raw;
    int ok = 1;
    for (int i = 0; i < 8; i++) {
        long long v = p[i];
        if (v < 0 || v >= (long long)N) ok = 0;
    }
    g_is64 = ok;
}

__global__ void zero_kernel(int N) {
    int i = blockIdx.x * blockDim.x + threadIdx.x;
    if (i < N) { g_cnt[i] = 0; g_cur[i] = 0; }
}

__global__ void convert_count_kernel(const void* ei_raw, int E) {
    int e = blockIdx.x * blockDim.x + threadIdx.x;
    if (e >= E) return;
    int r, c;
    if (g_is64) {
        const long long* p = (const long long*)ei_raw;
        r = (int)p[e];
        c = (int)p[(size_t)E + e];
    } else {
        const int* p = (const int*)ei_raw;
        r = p[e];
        c = p[E + e];
    }
    g_rows[e] = r;
    g_cols[e] = c;
    atomicAdd(&g_cnt[c], 1);
}

__global__ void scan_blocks_kernel(int N) {
    __shared__ int s[SCAN_BS];
    int i = blockIdx.x * SCAN_BS + threadIdx.x;
    int v = (i < N) ? g_cnt[i] : 0;
    s[threadIdx.x] = v;
    __syncthreads();
    for (int off = 1; off < SCAN_BS; off <<= 1) {
        int t = (threadIdx.x >= off) ? s[threadIdx.x - off] : 0;
        __syncthreads();
        s[threadIdx.x] += t;
        __syncthreads();
    }
    if (i < N) g_rowptr[i] = s[threadIdx.x] - v;
    if (threadIdx.x == SCAN_BS - 1) g_btot[blockIdx.x] = s[SCAN_BS - 1];
}

__global__ void scan_tops_kernel(int nblocks) {
    __shared__ int s[512];
    int v = (threadIdx.x < nblocks) ? g_btot[threadIdx.x] : 0;
    s[threadIdx.x] = v;
    __syncthreads();
    for (int off = 1; off < 512; off <<= 1) {
        int t = (threadIdx.x >= off) ? s[threadIdx.x - off] : 0;
        __syncthreads();
        s[threadIdx.x] += t;
        __syncthreads();
    }
    if (threadIdx.x < nblocks) g_boff[threadIdx.x] = s[threadIdx.x] - v;
}

__global__ void scan_add_kernel(int N, int E) {
    int i = blockIdx.x * SCAN_BS + threadIdx.x;
    if (i < N) g_rowptr[i] += g_boff[blockIdx.x];
    if (i == 0) g_rowptr[N] = E;
}

__global__ void finalize_dis_kernel(int N) {
    int i = blockIdx.x * blockDim.x + threadIdx.x;
    if (i < N) g_dis[i] = rsqrtf((float)g_cnt[i] + 1.0f);
}

__global__ void fill_csr_kernel(int E) {
    int e = blockIdx.x * blockDim.x + threadIdx.x;
    if (e >= E) return;
    int r = g_rows[e];
    int c = g_cols[e];
    int pos = g_rowptr[c] + atomicAdd(&g_cur[c], 1);
    g_csr_src[pos] = r;
    g_csr_norm[pos] = g_dis[r] * g_dis[c];
}

// Weight pre-conversion: W [K][F] fp32 -> whi/wlo [F][K] bf16 at given offset
__global__ void conv_w_kernel(const float* __restrict__ W, int K, int F, int off) {
    int idx = blockIdx.x * blockDim.x + threadIdx.x;
    if (idx >= K * F) return;
    int k = idx / F;
    int n = idx % F;
    float wv = W[idx];
    __nv_bfloat16 h = __float2bfloat16(wv);
    g_whi[off + n * K + k] = h;
    g_wlo[off + n * K + k] = __float2bfloat16(wv - __bfloat162float(h));
}

// ---------------------------------------------------------------------------
// PTX helpers (baseline sm_80+, compiles for compute_103)
// ---------------------------------------------------------------------------
__device__ __forceinline__ void mma16816(float* d, const uint32_t* a, const uint32_t* b) {
    asm volatile("mma.sync.aligned.m16n8k16.row.col.f32.bf16.bf16.f32 "
        "{%0,%1,%2,%3}, {%4,%5,%6,%7}, {%8,%9}, {%0,%1,%2,%3};"
        : "+f"(d[0]), "+f"(d[1]), "+f"(d[2]), "+f"(d[3])
        : "r"(a[0]), "r"(a[1]), "r"(a[2]), "r"(a[3]), "r"(b[0]), "r"(b[1]));
}
__device__ __forceinline__ void ldsm4(uint32_t* r, uint32_t addr) {
    asm volatile("ldmatrix.sync.aligned.m8n8.x4.shared.b16 {%0,%1,%2,%3}, [%4];"
        : "=r"(r[0]), "=r"(r[1]), "=r"(r[2]), "=r"(r[3]) : "r"(addr));
}
__device__ __forceinline__ void cpa16(uint32_t dst, const __nv_bfloat16* src, int bytes) {
    asm volatile("cp.async.cg.shared.global [%0], [%1], 16, %2;"
                 :: "r"(dst), "l"(src), "r"(bytes));
}
__device__ __forceinline__ uint32_t pack_bf16x2(float a, float b) {
    __nv_bfloat162 t = __nv_bfloat162(__float2bfloat16(a), __float2bfloat16(b));
    return *(uint32_t*)&t;
}

// ---------------------------------------------------------------------------
// Tensor-core GEMM, bf16 hi/lo 3-pass, cp.async double-buffered.
// Inputs: activations as preconverted hi/lo pairs [row][K]; weights [n][K].
// OMODE 0 (DUAL):  xw = D ; agg = D*dis[row]^2 + bias   (fp32, for csr_agg)
// OMODE 1 (SPLIT): O = D + bias        -> hi/lo bf16 pair
// OMODE 2 (SPLIT+RELU): O = relu(D + bias) -> hi/lo pair
// CTA tile 128x128, BK=32, 8 warps 4(m)x2(n).
// ---------------------------------------------------------------------------
template <int OMODE>
__global__ __launch_bounds__(256, 2)
void mma_gemm_kernel(const __nv_bfloat16* __restrict__ Ahi_g,
                     const __nv_bfloat16* __restrict__ Alo_g,
                     const __nv_bfloat16* __restrict__ whi,
                     const __nv_bfloat16* __restrict__ wlo,
                     const float* __restrict__ bias, const float* __restrict__ dis,
                     float* __restrict__ xw, float* __restrict__ agg,
                     __nv_bfloat16* __restrict__ Ohi, __nv_bfloat16* __restrict__ Olo,
                     int N, int K, int F)
{
    extern __shared__ __nv_bfloat16 sm[];   // [2][4][ARR]
    const uint32_t smBase = (uint32_t)__cvta_generic_to_shared(sm);

    const int tid = threadIdx.x;
    const int lane = tid & 31;
    const int w = tid >> 5;
    const int wm = w >> 1;
    const int wn = w & 1;
    const int m0 = blockIdx.x * 128;
    const int n0 = blockIdx.y * 128;

    // copy mapping: row = tid>>1, seg = (tid&1)*16 bf16
    const int crow = tid >> 1;
    const int cseg = (tid & 1) * 16;
    const int arow = m0 + crow;
    const int aval = (arow < N) ? 16 : 0;
    const int arowc = (arow < N) ? arow : 0;
    const __nv_bfloat16* aHi = Ahi_g + (size_t)arowc * K;
    const __nv_bfloat16* aLo = Alo_g + (size_t)arowc * K;
    const __nv_bfloat16* bHi = whi + (size_t)(n0 + crow) * K;
    const __nv_bfloat16* bLo = wlo + (size_t)(n0 + crow) * K;

#define LOAD_STAGE(st, k0) do {                                                  \
    uint32_t b_ = smBase + (uint32_t)(st) * (4 * ARR * 2);                       \
    uint32_t dA = b_ + (uint32_t)(crow * BKP + cseg) * 2;                        \
    cpa16(dA,                aHi + (k0) + cseg,     aval);                       \
    cpa16(dA + 16,           aHi + (k0) + cseg + 8, aval);                       \
    cpa16(dA + ARR * 2,      aLo + (k0) + cseg,     aval);                       \
    cpa16(dA + ARR * 2 + 16, aLo + (k0) + cseg + 8, aval);                       \
    cpa16(dA + 2 * ARR * 2,      bHi + (k0) + cseg,     16);                     \
    cpa16(dA + 2 * ARR * 2 + 16, bHi + (k0) + cseg + 8, 16);                     \
    cpa16(dA + 3 * ARR * 2,      bLo + (k0) + cseg,     16);                     \
    cpa16(dA + 3 * ARR * 2 + 16, bLo + (k0) + cseg + 8, 16);                     \
    asm volatile("cp.async.commit_group;");                                      \
} while (0)

    // ldmatrix per-lane coords
    const int t  = lane >> 3;
    const int tr = lane & 7;
    const int a_row_l = wm * 32 + (t & 1) * 8 + tr;
    const int a_koff  = (t >> 1) * 8;
    const int b_row_l = wn * 64 + (t >> 1) * 8 + tr;
    const int b_koff  = (t & 1) * 8;

    float acc[2][8][4];
#pragma unroll
    for (int mi = 0; mi < 2; mi++)
#pragma unroll
        for (int nf = 0; nf < 8; nf++)
#pragma unroll
            for (int c = 0; c < 4; c++) acc[mi][nf][c] = 0.f;

    const int nch = K >> 5;
    LOAD_STAGE(0, 0);

    for (int ch = 0; ch < nch; ch++) {
        if (ch + 1 < nch) {
            LOAD_STAGE((ch + 1) & 1, (ch + 1) << 5);
            asm volatile("cp.async.wait_group 1;");
        } else {
            asm volatile("cp.async.wait_group 0;");
        }
        __syncthreads();

        const uint32_t sb = smBase + (uint32_t)(ch & 1) * (4 * ARR * 2);
        const uint32_t aAhi = sb;
        const uint32_t aAlo = sb + ARR * 2;
        const uint32_t aBhi = sb + 2 * ARR * 2;
        const uint32_t aBlo = sb + 3 * ARR * 2;

#pragma unroll
        for (int s = 0; s < 2; s++) {
            const int kb = s * 16;
            uint32_t ahi[2][4], alo[2][4];
#pragma unroll
            for (int mi = 0; mi < 2; mi++) {
                uint32_t off = (uint32_t)(((a_row_l + mi * 16) * BKP + kb + a_koff) * 2);
                ldsm4(ahi[mi], aAhi + off);
                ldsm4(alo[mi], aAlo + off);
            }
            uint32_t bhi[8][2], blo[8][2];
#pragma unroll
            for (int q = 0; q < 4; q++) {
                uint32_t off = (uint32_t)(((b_row_l + q * 16) * BKP + kb + b_koff) * 2);
                uint32_t r4[4];
                ldsm4(r4, aBhi + off);
                bhi[2 * q][0] = r4[0]; bhi[2 * q][1] = r4[1];
                bhi[2 * q + 1][0] = r4[2]; bhi[2 * q + 1][1] = r4[3];
                ldsm4(r4, aBlo + off);
                blo[2 * q][0] = r4[0]; blo[2 * q][1] = r4[1];
                blo[2 * q + 1][0] = r4[2]; blo[2 * q + 1][1] = r4[3];
            }
#pragma unroll
            for (int mi = 0; mi < 2; mi++)
#pragma unroll
                for (int nf = 0; nf < 8; nf++) {
                    mma16816(acc[mi][nf], ahi[mi], bhi[nf]);
                    mma16816(acc[mi][nf], ahi[mi], blo[nf]);
                    mma16816(acc[mi][nf], alo[mi], bhi[nf]);
                }
        }
        __syncthreads();
    }
#undef LOAD_STAGE

    // ---- epilogue ----
    const int crow0 = m0 + wm * 32 + (lane >> 2);
    const int ccol0 = n0 + wn * 64 + (lane & 3) * 2;
#pragma unroll
    for (int mi = 0; mi < 2; mi++) {
        int r1 = crow0 + mi * 16;
        int r2 = r1 + 8;
        float d1 = 0.f, d2v = 0.f;
        if (OMODE == 0) {
            if (r1 < N) { float d = dis[r1]; d1 = d * d; }
            if (r2 < N) { float d = dis[r2]; d2v = d * d; }
        }
#pragma unroll
        for (int nf = 0; nf < 8; nf++) {
            int col = ccol0 + nf * 8;
            float b0 = bias[col], b1 = bias[col + 1];
#pragma unroll
            for (int half = 0; half < 2; half++) {
                int row = half ? r2 : r1;
                if (row >= N) continue;
                float vx = acc[mi][nf][half * 2 + 0];
                float vy = acc[mi][nf][half * 2 + 1];
                size_t o = (size_t)row * F + col;
                if (OMODE == 0) {
                    float dd = half ? d2v : d1;
                    *(float2*)(xw + o) = make_float2(vx, vy);
                    *(float2*)(agg + o) = make_float2(vx * dd + b0, vy * dd + b1);
                } else {
                    float sx = vx + b0, sy = vy + b1;
                    if (OMODE == 2) { sx = fmaxf(sx, 0.f); sy = fmaxf(sy, 0.f); }
                    __nv_bfloat16 hx = __float2bfloat16(sx), hy = __float2bfloat16(sy);
                    float lxf = sx - __bfloat162float(hx), lyf = sy - __bfloat162float(hy);
                    __nv_bfloat162 th = __nv_bfloat162(hx, hy);
                    __nv_bfloat162 tl = __nv_bfloat162(__float2bfloat16(lxf), __float2bfloat16(lyf));
                    *(uint32_t*)(Ohi + o) = *(uint32_t*)&th;
                    *(uint32_t*)(Olo + o) = *(uint32_t*)&tl;
                }
            }
        }
    }
}

// ---------------------------------------------------------------------------
// CSR gather-side aggregation (F=128, no atomics)
// MODE 0 (INIT_SPLIT): out_pair = gather(src) + dis^2 * src[node]
// MODE 1 (ADD_FP32):   aggf[node] += gather(src)           (in-place)
// MODE 2 (ADD_SPLIT):  out_pair = aggf[node] + gather(src)
// ---------------------------------------------------------------------------
template <int MODE>
__global__ __launch_bounds__(256)
void csr_agg_kernel(const float* __restrict__ src, float* __restrict__ aggf,
                    __nv_bfloat16* __restrict__ Ohi, __nv_bfloat16* __restrict__ Olo,
                    const float* __restrict__ dis, int N)
{
    const int lane = threadIdx.x & 31;
    const int node = (blockIdx.x * blockDim.x + threadIdx.x) >> 5;
    if (node >= N) return;

    int beg = g_rowptr[node];
    int end = g_rowptr[node + 1];
    if (MODE == 1 && beg == end) return;

    float4 acc = make_float4(0.f, 0.f, 0.f, 0.f);

    for (int base = beg; base < end; base += 32) {
        int n = min(32, end - base);
        int srcReg = 0; float nrReg = 0.f;
        if (lane < n) {
            srcReg = g_csr_src[base + lane];
            nrReg  = g_csr_norm[base + lane];
        }
        for (int k = 0; k < n; k++) {
            int   r = __shfl_sync(0xffffffffu, srcReg, k);
            float wv = __shfl_sync(0xffffffffu, nrReg, k);
            float4 v = ((const float4*)(src + (size_t)r * 128))[lane];
            acc.x += wv * v.x;
            acc.y += wv * v.y;
            acc.z += wv * v.z;
            acc.w += wv * v.w;
        }
    }

    if (MODE == 0) {
        float dd = dis[node];
        float d2 = dd * dd;
        float4 sv = ((const float4*)(src + (size_t)node * 128))[lane];
        acc.x += d2 * sv.x; acc.y += d2 * sv.y;
        acc.z += d2 * sv.z; acc.w += d2 * sv.w;
    } else if (MODE == 1) {
        float4* d = (float4*)(aggf + (size_t)node * 128);
        float4 cur = d[lane];
        cur.x += acc.x; cur.y += acc.y; cur.z += acc.z; cur.w += acc.w;
        d[lane] = cur;
        return;
    } else {
        float4 cur = ((const float4*)(aggf + (size_t)node * 128))[lane];
        acc.x += cur.x; acc.y += cur.y; acc.z += cur.z; acc.w += cur.w;
    }

    // split fp32 -> hi/lo bf16 pair, store 4 cols
    size_t o = (size_t)node * 128 + lane * 4;
    __nv_bfloat16 h0 = __float2bfloat16(acc.x), h1 = __float2bfloat16(acc.y);
    __nv_bfloat16 h2 = __float2bfloat16(acc.z), h3 = __float2bfloat16(acc.w);
    uint2 ph, pl;
    ph.x = pack_bf16x2(acc.x, acc.y);   // note: pack re-rounds identically
    ph.y = pack_bf16x2(acc.z, acc.w);
    pl.x = pack_bf16x2(acc.x - __bfloat162float(h0), acc.y - __bfloat162float(h1));
    pl.y = pack_bf16x2(acc.z - __bfloat162float(h2), acc.w - __bfloat162float(h3));
    *(uint2*)(Ohi + o) = ph;
    *(uint2*)(Olo + o) = pl;
}

// ---------------------------------------------------------------------------
// Heads (fp32 inputs)
// ---------------------------------------------------------------------------
__global__ __launch_bounds__(256)
void head16_kernel(const float* __restrict__ A, const float* __restrict__ Wc,
                   const float* __restrict__ bc, float* __restrict__ out, int N)
{
    __shared__ float Ws[128 * 16];
    __shared__ float bs[16];
    for (int i = threadIdx.x; i < 128 * 16; i += 256) Ws[i] = Wc[i];
    if (threadIdx.x < 16) bs[threadIdx.x] = bc[threadIdx.x];
    __syncthreads();

    int j = threadIdx.x & 15;
    int rl = threadIdx.x >> 4;
    int row = blockIdx.x * 16 + rl;
    if (row >= N) return;

    const float* a = A + (size_t)row * 128;
    float acc = 0.f;
#pragma unroll 8
    for (int k = 0; k < 128; k++) acc += a[k] * Ws[k * 16 + j];
    out[(size_t)row * 16 + j] = acc + bs[j];
}

__global__ __launch_bounds__(256)
void head2_sigmoid_kernel(const float* __restrict__ A, const float* __restrict__ Wt,
                          const float* __restrict__ bt, float* __restrict__ out, int N)
{
    __shared__ float Ws[128 * 2];
    __shared__ float bs[2];
    for (int i = threadIdx.x; i < 128 * 2; i += 256) Ws[i] = Wt[i];
    if (threadIdx.x < 2) bs[threadIdx.x] = bt[threadIdx.x];
    __syncthreads();

    int j = threadIdx.x & 1;
    int rl = threadIdx.x >> 1;
    int row = blockIdx.x * 128 + rl;
    if (row >= N) return;

    const float* a = A + (size_t)row * 128;
    float acc = 0.f;
#pragma unroll 8
    for (int k = 0; k < 128; k++) acc += a[k] * Ws[k * 2 + j];
    float z = acc + bs[j];
    out[(size_t)row * 2 + j] = 1.0f / (1.0f + expf(-z));
}

// ---------------------------------------------------------------------------
// Launch
// ---------------------------------------------------------------------------
extern "C" void kernel_launch(void* const* d_in, const int* in_sizes, int n_in,
                              void* d_out, int out_size)
{
    const float* x = (const float*)d_in[0];
    const void* ei = d_in[1];
    const float* W1  = (const float*)d_in[2];
    const float* b1  = (const float*)d_in[3];
    const float* W2  = (const float*)d_in[4];
    const float* b2  = (const float*)d_in[5];
    const float* Wc  = (const float*)d_in[6];
    const float* bc  = (const float*)d_in[7];
    const float* We1 = (const float*)d_in[8];
    const float* be1 = (const float*)d_in[9];
    const float* We2 = (const float*)d_in[10];
    const float* be2 = (const float*)d_in[11];
    const float* We3 = (const float*)d_in[12];
    const float* be3 = (const float*)d_in[13];
    const float* We4 = (const float*)d_in[14];
    const float* be4 = (const float*)d_in[15];
    const float* Wt  = (const float*)d_in[16];
    const float* bt  = (const float*)d_in[17];
    float* out = (float*)d_out;

    const int N = in_sizes[0] / 128;
    const int E = in_sizes[1] / 2;
    const int nscan = (N + SCAN_BS - 1) / SCAN_BS;

    float *dis, *xw, *agg, *agg2;
    __nv_bfloat16 *whi, *wlo, *pAhi, *pAlo, *pBhi, *pBlo, *pChi, *pClo, *pDhi, *pDlo;
    cudaGetSymbolAddress((void**)&dis, g_dis);
    cudaGetSymbolAddress((void**)&xw, g_xw);
    cudaGetSymbolAddress((void**)&agg, g_agg);
    cudaGetSymbolAddress((void**)&agg2, g_agg2);
    cudaGetSymbolAddress((void**)&whi, g_whi);
    cudaGetSymbolAddress((void**)&wlo, g_wlo);
    cudaGetSymbolAddress((void**)&pAhi, g_pAhi);
    cudaGetSymbolAddress((void**)&pAlo, g_pAlo);
    cudaGetSymbolAddress((void**)&pBhi, g_pBhi);
    cudaGetSymbolAddress((void**)&pBlo, g_pBlo);
    cudaGetSymbolAddress((void**)&pChi, g_pChi);
    cudaGetSymbolAddress((void**)&pClo, g_pClo);
    cudaGetSymbolAddress((void**)&pDhi, g_pDhi);
    cudaGetSymbolAddress((void**)&pDlo, g_pDlo);

    cudaFuncSetAttribute(mma_gemm_kernel<0>, cudaFuncAttributeMaxDynamicSharedMemorySize, GEMM_SMEM);
    cudaFuncSetAttribute(mma_gemm_kernel<1>, cudaFuncAttributeMaxDynamicSharedMemorySize, GEMM_SMEM);
    cudaFuncSetAttribute(mma_gemm_kernel<2>, cudaFuncAttributeMaxDynamicSharedMemorySize, GEMM_SMEM);

    // weight offsets in g_whi/g_wlo: [n][k] per layer
    const int OFF_W1 = 0;
    const int OFF_W2 = 32768;
    const int OFF_E1 = 65536;
    const int OFF_E2 = 81920;
    const int OFF_E3 = 98304;
    const int OFF_E4 = 114688;

    // --- preprocessing ---
    detect_dtype_kernel<<<1, 1>>>(ei, N);
    zero_kernel<<<(N + 255) / 256, 256>>>(N);
    convert_count_kernel<<<(E + 255) / 256, 256>>>(ei, E);
    scan_blocks_kernel<<<nscan, SCAN_BS>>>(N);
    scan_tops_kernel<<<1, 512>>>(nscan);
    scan_add_kernel<<<nscan, SCAN_BS>>>(N, E);
    finalize_dis_kernel<<<(N + 255) / 256, 256>>>(N);
    fill_csr_kernel<<<(E + 255) / 256, 256>>>(E);
    conv_w_kernel<<<128, 256>>>(W1, 128, 256, OFF_W1);
    conv_w_kernel<<<128, 256>>>(W2, 256, 128, OFF_W2);
    conv_w_kernel<<<64, 256>>>(We1, 128, 128, OFF_E1);
    conv_w_kernel<<<64, 256>>>(We2, 128, 128, OFF_E2);
    conv_w_kernel<<<64, 256>>>(We3, 128, 128, OFF_E3);
    conv_w_kernel<<<64, 256>>>(We4, 128, 128, OFF_E4);

    dim3 gw((N + 127) / 128, 2);   // F=256
    dim3 g1((N + 127) / 128, 1);   // F=128
    const int AGG_BLOCKS = (N + 7) / 8;

    // --- shared propagated input: D = split(aggx) ---
    csr_agg_kernel<0><<<AGG_BLOCKS, 256>>>(x, nullptr, pDhi, pDlo, dis, N);

    // --- classification branch ---
    // A = split(relu(D @ W1 + b1))
    mma_gemm_kernel<2><<<gw, 256, GEMM_SMEM>>>(pDhi, pDlo, whi + OFF_W1, wlo + OFF_W1,
                                               b1, dis, nullptr, nullptr, pAhi, pAlo, N, 128, 256);
    // xw = A @ W2 ; agg = xw*dis^2 + b2 ; agg += edges ; head16
    mma_gemm_kernel<0><<<g1, 256, GEMM_SMEM>>>(pAhi, pAlo, whi + OFF_W2, wlo + OFF_W2,
                                               b2, dis, xw, agg, nullptr, nullptr, N, 256, 128);
    csr_agg_kernel<1><<<AGG_BLOCKS, 256>>>(xw, agg, nullptr, nullptr, dis, N);
    head16_kernel<<<(N + 15) / 16, 256>>>(agg, Wc, bc, out, N);

    // --- encoder branch ---
    // B = split(D @ We1 + be1)
    mma_gemm_kernel<1><<<g1, 256, GEMM_SMEM>>>(pDhi, pDlo, whi + OFF_E1, wlo + OFF_E1,
                                               be1, dis, nullptr, nullptr, pBhi, pBlo, N, 128, 128);
    mma_gemm_kernel<0><<<g1, 256, GEMM_SMEM>>>(pBhi, pBlo, whi + OFF_E2, wlo + OFF_E2,
                                               be2, dis, xw, agg2, nullptr, nullptr, N, 128, 128);
    csr_agg_kernel<2><<<AGG_BLOCKS, 256>>>(xw, agg2, pChi, pClo, dis, N);
    mma_gemm_kernel<0><<<g1, 256, GEMM_SMEM>>>(pChi, pClo, whi + OFF_E3, wlo + OFF_E3,
                                               be3, dis, xw, agg2, nullptr, nullptr, N, 128, 128);
    csr_agg_kernel<2><<<AGG_BLOCKS, 256>>>(xw, agg2, pBhi, pBlo, dis, N);
    mma_gemm_kernel<0><<<g1, 256, GEMM_SMEM>>>(pBhi, pBlo, whi + OFF_E4, wlo + OFF_E4,
                                               be4, dis, xw, agg2, nullptr, nullptr, N, 128, 128);
    csr_agg_kernel<1><<<AGG_BLOCKS, 256>>>(xw, agg2, nullptr, nullptr, dis, N);
    head2_sigmoid_kernel<<<(N + 127) / 128, 256>>>(agg2, Wt, bt, out + (size_t)N * 16, N);
}

// round 11
// speedup vs baseline: 2.0952x; 2.0952x over previous
#include <cuda_runtime.h>
#include <cuda_bf16.h>
#include <cstdint>
#include <math.h>

#define NNODES 100000
#define NEDGES 1600000
#define SCAN_BS 256
#define BKP 40
#define ARR (128 * BKP)
#define GEMM_SMEM (2 * 4 * ARR * 2)   // 81920 B

// ---------------------------------------------------------------------------
// Scratch (device globals)
// ---------------------------------------------------------------------------
__device__ float g_dis[NNODES];
__device__ __nv_bfloat16 g_pDhi[(size_t)NNODES * 128], g_pDlo[(size_t)NNODES * 128]; // aggx split
__device__ __nv_bfloat16 g_pAhi[(size_t)NNODES * 256], g_pAlo[(size_t)NNODES * 256]; // r split
__device__ float g_z[(size_t)NNODES * 16];
__device__ float g_y[(size_t)NNODES * 2];
__device__ float g_y2[(size_t)NNODES * 2];
__device__ int   g_rows[NEDGES];
__device__ int   g_cols[NEDGES];
__device__ int   g_cnt[NNODES];
__device__ int   g_cur[NNODES];
__device__ int   g_rowptr[NNODES + 1];
__device__ int   g_btot[(NNODES + SCAN_BS - 1) / SCAN_BS + 1];
__device__ int   g_boff[(NNODES + SCAN_BS - 1) / SCAN_BS + 1];
__device__ int   g_csr_src[NEDGES];
__device__ float g_csr_norm[NEDGES];
__device__ int   g_is64;
__device__ __nv_bfloat16 g_whi[32768], g_wlo[32768];       // W1 [n][k] split
__device__ __nv_bfloat16 g_Ghi[4096], g_Glo[4096];          // G=W2Wc, [j][k] split (16x256)
__device__ float g_c0[16];
__device__ float g_q[256];        // q[k*2+j]
__device__ float g_s[4][2];

// ---------------------------------------------------------------------------
// Preprocessing
// ---------------------------------------------------------------------------
__global__ void detect_dtype_kernel(const void* ei_raw, int N) {
    const long long* p = (const long long*)ei_raw;
    int ok = 1;
    for (int i = 0; i < 8; i++) {
        long long v = p[i];
        if (v < 0 || v >= (long long)N) ok = 0;
    }
    g_is64 = ok;
}

__global__ void zero_kernel(int N) {
    int i = blockIdx.x * blockDim.x + threadIdx.x;
    if (i < N) { g_cnt[i] = 0; g_cur[i] = 0; }
}

__global__ void convert_count_kernel(const void* ei_raw, int E) {
    int e = blockIdx.x * blockDim.x + threadIdx.x;
    if (e >= E) return;
    int r, c;
    if (g_is64) {
        const long long* p = (const long long*)ei_raw;
        r = (int)p[e];
        c = (int)p[(size_t)E + e];
    } else {
        const int* p = (const int*)ei_raw;
        r = p[e];
        c = p[E + e];
    }
    g_rows[e] = r;
    g_cols[e] = c;
    atomicAdd(&g_cnt[c], 1);
}

__global__ void scan_blocks_kernel(int N) {
    __shared__ int s[SCAN_BS];
    int i = blockIdx.x * SCAN_BS + threadIdx.x;
    int v = (i < N) ? g_cnt[i] : 0;
    s[threadIdx.x] = v;
    __syncthreads();
    for (int off = 1; off < SCAN_BS; off <<= 1) {
        int t = (threadIdx.x >= off) ? s[threadIdx.x - off] : 0;
        __syncthreads();
        s[threadIdx.x] += t;
        __syncthreads();
    }
    if (i < N) g_rowptr[i] = s[threadIdx.x] - v;
    if (threadIdx.x == SCAN_BS - 1) g_btot[blockIdx.x] = s[SCAN_BS - 1];
}

__global__ void scan_tops_kernel(int nblocks) {
    __shared__ int s[512];
    int v = (threadIdx.x < nblocks) ? g_btot[threadIdx.x] : 0;
    s[threadIdx.x] = v;
    __syncthreads();
    for (int off = 1; off < 512; off <<= 1) {
        int t = (threadIdx.x >= off) ? s[threadIdx.x - off] : 0;
        __syncthreads();
        s[threadIdx.x] += t;
        __syncthreads();
    }
    if (threadIdx.x < nblocks) g_boff[threadIdx.x] = s[threadIdx.x] - v;
}

__global__ void scan_add_kernel(int N, int E) {
    int i = blockIdx.x * SCAN_BS + threadIdx.x;
    if (i < N) g_rowptr[i] += g_boff[blockIdx.x];
    if (i == 0) g_rowptr[N] = E;
}

__global__ void finalize_dis_kernel(int N) {
    int i = blockIdx.x * blockDim.x + threadIdx.x;
    if (i < N) g_dis[i] = rsqrtf((float)g_cnt[i] + 1.0f);
}

__global__ void fill_csr_kernel(int E) {
    int e = blockIdx.x * blockDim.x + threadIdx.x;
    if (e >= E) return;
    int r = g_rows[e];
    int c = g_cols[e];
    int pos = g_rowptr[c] + atomicAdd(&g_cur[c], 1);
    g_csr_src[pos] = r;
    g_csr_norm[pos] = g_dis[r] * g_dis[c];
}

// W1 [K=128][F=256] fp32 -> whi/wlo [F][K] bf16
__global__ void conv_w_kernel(const float* __restrict__ W) {
    int idx = blockIdx.x * blockDim.x + threadIdx.x;
    if (idx >= 128 * 256) return;
    int k = idx / 256;
    int n = idx % 256;
    float wv = W[idx];
    __nv_bfloat16 h = __float2bfloat16(wv);
    g_whi[n * 128 + k] = h;
    g_wlo[n * 128 + k] = __float2bfloat16(wv - __bfloat162float(h));
}

// G = W2 @ Wc (256x16) -> split [j][k]; c0 = b2ᵀWc + bc. grid=16, block=256.
__global__ void gwc_kernel(const float* __restrict__ W2, const float* __restrict__ Wc,
                           const float* __restrict__ b2, const float* __restrict__ bc) {
    int j = blockIdx.x;
    int m = threadIdx.x;     // 0..255 (H1 index)
    float s = 0.f;
    for (int k = 0; k < 128; k++) s += W2[m * 128 + k] * Wc[k * 16 + j];
    __nv_bfloat16 h = __float2bfloat16(s);
    g_Ghi[j * 256 + m] = h;
    g_Glo[j * 256 + m] = __float2bfloat16(s - __bfloat162float(h));
    if (m == 0) {
        float c = 0.f;
        for (int k = 0; k < 128; k++) c += b2[k] * Wc[k * 16 + j];
        g_c0[j] = c + bc[j];
    }
}

// Encoder weight chain (1 block, 256 threads):
// t4=We4Wt; t3=We3t4; t2=We2t3; q=We1t2; s1=be1ᵀt2; s2=be2ᵀt3; s3=be3ᵀt4; s4=be4ᵀWt+bt
__global__ void enc_chain_kernel(const float* We1, const float* We2, const float* We3,
                                 const float* We4, const float* Wt,
                                 const float* be1, const float* be2, const float* be3,
                                 const float* be4, const float* bt) {
    __shared__ float a[256], b[256];
    int tid = threadIdx.x;
    int row = tid >> 1, j = tid & 1;
    float s;

    // a = t4 = We4 @ Wt
    s = 0.f;
    for (int k = 0; k < 128; k++) s += We4[row * 128 + k] * Wt[k * 2 + j];
    a[tid] = s;
    __syncthreads();

    if (tid < 2) {
        float acc = 0.f;
        for (int k = 0; k < 128; k++) acc += be3[k] * a[k * 2 + tid];
        g_s[2][tid] = acc;                              // s3
        float a4 = 0.f;
        for (int k = 0; k < 128; k++) a4 += be4[k] * Wt[k * 2 + tid];
        g_s[3][tid] = a4 + bt[tid];                     // s4 + bt
    }
    // b = t3 = We3 @ t4
    s = 0.f;
    for (int k = 0; k < 128; k++) s += We3[row * 128 + k] * a[k * 2 + j];
    b[tid] = s;
    __syncthreads();

    if (tid < 2) {
        float acc = 0.f;
        for (int k = 0; k < 128; k++) acc += be2[k] * b[k * 2 + tid];
        g_s[1][tid] = acc;                              // s2
    }
    // a = t2 = We2 @ t3
    s = 0.f;
    for (int k = 0; k < 128; k++) s += We2[row * 128 + k] * b[k * 2 + j];
    __syncthreads();          // all reads of old a done
    a[tid] = s;
    __syncthreads();

    if (tid < 2) {
        float acc = 0.f;
        for (int k = 0; k < 128; k++) acc += be1[k] * a[k * 2 + tid];
        g_s[0][tid] = acc;                              // s1
    }
    // q = We1 @ t2
    s = 0.f;
    for (int k = 0; k < 128; k++) s += We1[row * 128 + k] * a[k * 2 + j];
    g_q[tid] = s;
}

// ---------------------------------------------------------------------------
// PTX helpers
// ---------------------------------------------------------------------------
__device__ __forceinline__ void mma16816(float* d, const uint32_t* a, const uint32_t* b) {
    asm volatile("mma.sync.aligned.m16n8k16.row.col.f32.bf16.bf16.f32 "
        "{%0,%1,%2,%3}, {%4,%5,%6,%7}, {%8,%9}, {%0,%1,%2,%3};"
        : "+f"(d[0]), "+f"(d[1]), "+f"(d[2]), "+f"(d[3])
        : "r"(a[0]), "r"(a[1]), "r"(a[2]), "r"(a[3]), "r"(b[0]), "r"(b[1]));
}
__device__ __forceinline__ void ldsm4(uint32_t* r, uint32_t addr) {
    asm volatile("ldmatrix.sync.aligned.m8n8.x4.shared.b16 {%0,%1,%2,%3}, [%4];"
        : "=r"(r[0]), "=r"(r[1]), "=r"(r[2]), "=r"(r[3]) : "r"(addr));
}
__device__ __forceinline__ void cpa16(uint32_t dst, const __nv_bfloat16* src, int bytes) {
    asm volatile("cp.async.cg.shared.global [%0], [%1], 16, %2;"
                 :: "r"(dst), "l"(src), "r"(bytes));
}

// ---------------------------------------------------------------------------
// Main GEMM (128x128 tile, bf16 hi/lo 3-pass, cp.async 2-stage)
// OMODE 2: O = split(relu(D + bias))
// ---------------------------------------------------------------------------
template <int OMODE>
__global__ __launch_bounds__(256, 2)
void mma_gemm_kernel(const __nv_bfloat16* __restrict__ Ahi_g,
                     const __nv_bfloat16* __restrict__ Alo_g,
                     const __nv_bfloat16* __restrict__ whi,
                     const __nv_bfloat16* __restrict__ wlo,
                     const float* __restrict__ bias,
                     __nv_bfloat16* __restrict__ Ohi, __nv_bfloat16* __restrict__ Olo,
                     int N, int K, int F)
{
    extern __shared__ __nv_bfloat16 sm[];
    const uint32_t smBase = (uint32_t)__cvta_generic_to_shared(sm);

    const int tid = threadIdx.x;
    const int lane = tid & 31;
    const int w = tid >> 5;
    const int wm = w >> 1;
    const int wn = w & 1;
    const int m0 = blockIdx.x * 128;
    const int n0 = blockIdx.y * 128;

    const int crow = tid >> 1;
    const int cseg = (tid & 1) * 16;
    const int arow = m0 + crow;
    const int aval = (arow < N) ? 16 : 0;
    const int arowc = (arow < N) ? arow : 0;
    const __nv_bfloat16* aHi = Ahi_g + (size_t)arowc * K;
    const __nv_bfloat16* aLo = Alo_g + (size_t)arowc * K;
    const __nv_bfloat16* bHi = whi + (size_t)(n0 + crow) * K;
    const __nv_bfloat16* bLo = wlo + (size_t)(n0 + crow) * K;

#define LOAD_STAGE(st, k0) do {                                                  \
    uint32_t b_ = smBase + (uint32_t)(st) * (4 * ARR * 2);                       \
    uint32_t dA = b_ + (uint32_t)(crow * BKP + cseg) * 2;                        \
    cpa16(dA,                aHi + (k0) + cseg,     aval);                       \
    cpa16(dA + 16,           aHi + (k0) + cseg + 8, aval);                       \
    cpa16(dA + ARR * 2,      aLo + (k0) + cseg,     aval);                       \
    cpa16(dA + ARR * 2 + 16, aLo + (k0) + cseg + 8, aval);                       \
    cpa16(dA + 2 * ARR * 2,      bHi + (k0) + cseg,     16);                     \
    cpa16(dA + 2 * ARR * 2 + 16, bHi + (k0) + cseg + 8, 16);                     \
    cpa16(dA + 3 * ARR * 2,      bLo + (k0) + cseg,     16);                     \
    cpa16(dA + 3 * ARR * 2 + 16, bLo + (k0) + cseg + 8, 16);                     \
    asm volatile("cp.async.commit_group;");                                      \
} while (0)

    const int t  = lane >> 3;
    const int tr = lane & 7;
    const int a_row_l = wm * 32 + (t & 1) * 8 + tr;
    const int a_koff  = (t >> 1) * 8;
    const int b_row_l = wn * 64 + (t >> 1) * 8 + tr;
    const int b_koff  = (t & 1) * 8;

    float acc[2][8][4];
#pragma unroll
    for (int mi = 0; mi < 2; mi++)
#pragma unroll
        for (int nf = 0; nf < 8; nf++)
#pragma unroll
            for (int c = 0; c < 4; c++) acc[mi][nf][c] = 0.f;

    const int nch = K >> 5;
    LOAD_STAGE(0, 0);

    for (int ch = 0; ch < nch; ch++) {
        if (ch + 1 < nch) {
            LOAD_STAGE((ch + 1) & 1, (ch + 1) << 5);
            asm volatile("cp.async.wait_group 1;");
        } else {
            asm volatile("cp.async.wait_group 0;");
        }
        __syncthreads();

        const uint32_t sb = smBase + (uint32_t)(ch & 1) * (4 * ARR * 2);
        const uint32_t aAhi = sb;
        const uint32_t aAlo = sb + ARR * 2;
        const uint32_t aBhi = sb + 2 * ARR * 2;
        const uint32_t aBlo = sb + 3 * ARR * 2;

#pragma unroll
        for (int s = 0; s < 2; s++) {
            const int kb = s * 16;
            uint32_t ahi[2][4], alo[2][4];
#pragma unroll
            for (int mi = 0; mi < 2; mi++) {
                uint32_t off = (uint32_t)(((a_row_l + mi * 16) * BKP + kb + a_koff) * 2);
                ldsm4(ahi[mi], aAhi + off);
                ldsm4(alo[mi], aAlo + off);
            }
            uint32_t bhi[8][2], blo[8][2];
#pragma unroll
            for (int q = 0; q < 4; q++) {
                uint32_t off = (uint32_t)(((b_row_l + q * 16) * BKP + kb + b_koff) * 2);
                uint32_t r4[4];
                ldsm4(r4, aBhi + off);
                bhi[2 * q][0] = r4[0]; bhi[2 * q][1] = r4[1];
                bhi[2 * q + 1][0] = r4[2]; bhi[2 * q + 1][1] = r4[3];
                ldsm4(r4, aBlo + off);
                blo[2 * q][0] = r4[0]; blo[2 * q][1] = r4[1];
                blo[2 * q + 1][0] = r4[2]; blo[2 * q + 1][1] = r4[3];
            }
#pragma unroll
            for (int mi = 0; mi < 2; mi++)
#pragma unroll
                for (int nf = 0; nf < 8; nf++) {
                    mma16816(acc[mi][nf], ahi[mi], bhi[nf]);
                    mma16816(acc[mi][nf], ahi[mi], blo[nf]);
                    mma16816(acc[mi][nf], alo[mi], bhi[nf]);
                }
        }
        __syncthreads();
    }
#undef LOAD_STAGE

    const int crow0 = m0 + wm * 32 + (lane >> 2);
    const int ccol0 = n0 + wn * 64 + (lane & 3) * 2;
#pragma unroll
    for (int mi = 0; mi < 2; mi++) {
        int r1 = crow0 + mi * 16;
        int r2 = r1 + 8;
#pragma unroll
        for (int nf = 0; nf < 8; nf++) {
            int col = ccol0 + nf * 8;
            float b0 = bias[col], b1 = bias[col + 1];
#pragma unroll
            for (int half = 0; half < 2; half++) {
                int row = half ? r2 : r1;
                if (row >= N) continue;
                float sx = acc[mi][nf][half * 2 + 0] + b0;
                float sy = acc[mi][nf][half * 2 + 1] + b1;
                if (OMODE == 2) { sx = fmaxf(sx, 0.f); sy = fmaxf(sy, 0.f); }
                size_t o = (size_t)row * F + col;
                __nv_bfloat16 hx = __float2bfloat16(sx), hy = __float2bfloat16(sy);
                float lxf = sx - __bfloat162float(hx), lyf = sy - __bfloat162float(hy);
                __nv_bfloat162 th = __nv_bfloat162(hx, hy);
                __nv_bfloat162 tl = __nv_bfloat162(__float2bfloat16(lxf), __float2bfloat16(lyf));
                *(uint32_t*)(Ohi + o) = *(uint32_t*)&th;
                *(uint32_t*)(Olo + o) = *(uint32_t*)&tl;
            }
        }
    }
}

// ---------------------------------------------------------------------------
// Skinny tensor GEMM: z = r(N x 256) @ G(256 x 16), fp32 out.
// CTA: 128 rows x 16 cols; 8 warps, 16 rows each. B (G) staged once.
// ---------------------------------------------------------------------------
__global__ __launch_bounds__(256)
void zmma_kernel(const __nv_bfloat16* __restrict__ rhi,
                 const __nv_bfloat16* __restrict__ rlo,
                 float* __restrict__ z, int N)
{
    __shared__ __nv_bfloat16 sAhi[128 * BKP];
    __shared__ __nv_bfloat16 sAlo[128 * BKP];
    __shared__ __nv_bfloat16 sBhi[16 * 264];
    __shared__ __nv_bfloat16 sBlo[16 * 264];

    const int tid = threadIdx.x;
    const int lane = tid & 31;
    const int w = tid >> 5;
    const int m0 = blockIdx.x * 128;

    const uint32_t aAhi = (uint32_t)__cvta_generic_to_shared(sAhi);
    const uint32_t aAlo = (uint32_t)__cvta_generic_to_shared(sAlo);
    const uint32_t aBhi = (uint32_t)__cvta_generic_to_shared(sBhi);
    const uint32_t aBlo = (uint32_t)__cvta_generic_to_shared(sBlo);

    // stage G once: [16][256] -> stride 264
    for (int i = tid; i < 16 * 256; i += 256) {
        int n = i >> 8, k = i & 255;
        sBhi[n * 264 + k] = g_Ghi[i];
        sBlo[n * 264 + k] = g_Glo[i];
    }

    const int t  = lane >> 3;
    const int tr = lane & 7;
    const int a_row_l = w * 16 + (t & 1) * 8 + tr;
    const int a_koff  = (t >> 1) * 8;
    const int b_row_l = (t >> 1) * 8 + tr;
    const int b_koff  = (t & 1) * 8;

    const int crow = tid >> 1;
    const int cseg = (tid & 1) * 16;
    const int arow = m0 + crow;

    float acc[2][4];
#pragma unroll
    for (int nf = 0; nf < 2; nf++)
#pragma unroll
        for (int c = 0; c < 4; c++) acc[nf][c] = 0.f;

    for (int ch = 0; ch < 8; ch++) {
        const int k0 = ch * 32;
        // stage A chunk 128x32 (pairs)
        uint4 vh = make_uint4(0, 0, 0, 0), vl = vh, vh2 = vh, vl2 = vh;
        if (arow < N) {
            const __nv_bfloat16* ph = rhi + (size_t)arow * 256 + k0 + cseg;
            const __nv_bfloat16* pl = rlo + (size_t)arow * 256 + k0 + cseg;
            vh = *(const uint4*)ph;  vh2 = *(const uint4*)(ph + 8);
            vl = *(const uint4*)pl;  vl2 = *(const uint4*)(pl + 8);
        }
        __syncthreads();   // previous chunk's mma done before overwrite
        *(uint4*)&sAhi[crow * BKP + cseg] = vh;
        *(uint4*)&sAhi[crow * BKP + cseg + 8] = vh2;
        *(uint4*)&sAlo[crow * BKP + cseg] = vl;
        *(uint4*)&sAlo[crow * BKP + cseg + 8] = vl2;
        __syncthreads();

#pragma unroll
        for (int s = 0; s < 2; s++) {
            const int kb = s * 16;
            uint32_t ahi[4], alo[4];
            uint32_t offA = (uint32_t)((a_row_l * BKP + kb + a_koff) * 2);
            ldsm4(ahi, aAhi + offA);
            ldsm4(alo, aAlo + offA);
            uint32_t bhi[2][2], blo[2][2];
            uint32_t offB = (uint32_t)((b_row_l * 264 + k0 + kb + b_koff) * 2);
            uint32_t r4[4];
            ldsm4(r4, aBhi + offB);
            bhi[0][0] = r4[0]; bhi[0][1] = r4[1];
            bhi[1][0] = r4[2]; bhi[1][1] = r4[3];
            ldsm4(r4, aBlo + offB);
            blo[0][0] = r4[0]; blo[0][1] = r4[1];
            blo[1][0] = r4[2]; blo[1][1] = r4[3];
#pragma unroll
            for (int nf = 0; nf < 2; nf++) {
                mma16816(acc[nf], ahi, bhi[nf]);
                mma16816(acc[nf], ahi, blo[nf]);
                mma16816(acc[nf], alo, bhi[nf]);
            }
        }
    }

    // epilogue: rows w*16 + (lane>>2) (+8); cols (lane&3)*2 + nf*8
    const int crow0 = m0 + w * 16 + (lane >> 2);
    const int ccol0 = (lane & 3) * 2;
#pragma unroll
    for (int nf = 0; nf < 2; nf++) {
        int col = ccol0 + nf * 8;
#pragma unroll
        for (int half = 0; half < 2; half++) {
            int row = crow0 + half * 8;
            if (row < N) {
                size_t o = (size_t)row * 16 + col;
                z[o]     = acc[nf][half * 2 + 0];
                z[o + 1] = acc[nf][half * 2 + 1];
            }
        }
    }
}

// ---------------------------------------------------------------------------
// aggx: split(M x)  (warp per node; gathers fp32 x, writes hi/lo pairs)
// ---------------------------------------------------------------------------
__global__ __launch_bounds__(256)
void aggx_kernel(const float* __restrict__ x,
                 __nv_bfloat16* __restrict__ Ohi, __nv_bfloat16* __restrict__ Olo,
                 const float* __restrict__ dis, int N)
{
    const int lane = threadIdx.x & 31;
    const int node = (blockIdx.x * blockDim.x + threadIdx.x) >> 5;
    if (node >= N) return;

    int beg = g_rowptr[node];
    int end = g_rowptr[node + 1];

    float4 acc = make_float4(0.f, 0.f, 0.f, 0.f);
    for (int base = beg; base < end; base += 32) {
        int n = min(32, end - base);
        int srcReg = 0; float nrReg = 0.f;
        if (lane < n) {
            srcReg = g_csr_src[base + lane];
            nrReg  = g_csr_norm[base + lane];
        }
        for (int k = 0; k < n; k++) {
            int   r = __shfl_sync(0xffffffffu, srcReg, k);
            float wv = __shfl_sync(0xffffffffu, nrReg, k);
            float4 v = ((const float4*)(x + (size_t)r * 128))[lane];
            acc.x += wv * v.x; acc.y += wv * v.y;
            acc.z += wv * v.z; acc.w += wv * v.w;
        }
    }
    float dd = dis[node];
    float d2 = dd * dd;
    float4 sv = ((const float4*)(x + (size_t)node * 128))[lane];
    acc.x += d2 * sv.x; acc.y += d2 * sv.y;
    acc.z += d2 * sv.z; acc.w += d2 * sv.w;

    size_t o = (size_t)node * 128 + lane * 4;
    __nv_bfloat16 h0 = __float2bfloat16(acc.x), h1 = __float2bfloat16(acc.y);
    __nv_bfloat16 h2 = __float2bfloat16(acc.z), h3 = __float2bfloat16(acc.w);
    __nv_bfloat162 t01 = __nv_bfloat162(h0, h1), t23 = __nv_bfloat162(h2, h3);
    __nv_bfloat162 l01 = __nv_bfloat162(__float2bfloat16(acc.x - __bfloat162float(h0)),
                                        __float2bfloat16(acc.y - __bfloat162float(h1)));
    __nv_bfloat162 l23 = __nv_bfloat162(__float2bfloat16(acc.z - __bfloat162float(h2)),
                                        __float2bfloat16(acc.w - __bfloat162float(h3)));
    uint2 ph, pl;
    ph.x = *(uint32_t*)&t01; ph.y = *(uint32_t*)&t23;
    pl.x = *(uint32_t*)&l01; pl.y = *(uint32_t*)&l23;
    *(uint2*)(Ohi + o) = ph;
    *(uint2*)(Olo + o) = pl;
}

// ---------------------------------------------------------------------------
// prop16: out = M z + c0  (logits). Warp per node, half-warps split edges.
// ---------------------------------------------------------------------------
__global__ __launch_bounds__(256)
void prop16_kernel(const float* __restrict__ z, float* __restrict__ outp,
                   const float* __restrict__ dis, int N)
{
    const int lane = threadIdx.x & 31;
    const int node = (blockIdx.x * blockDim.x + threadIdx.x) >> 5;
    if (node >= N) return;

    int beg = g_rowptr[node];
    int end = g_rowptr[node + 1];
    int hw = lane >> 4, f = lane & 15;

    float acc = 0.f;
    for (int e = beg + hw; e < end; e += 2) {
        int r = g_csr_src[e];
        float wv = g_csr_norm[e];
        acc += wv * z[(size_t)r * 16 + f];
    }
    acc += __shfl_xor_sync(0xffffffffu, acc, 16);
    if (hw == 0) {
        float dd = dis[node];
        outp[(size_t)node * 16 + f] = acc + dd * dd * z[(size_t)node * 16 + f] + g_c0[f];
    }
}

// ---------------------------------------------------------------------------
// y = x @ q (N x 2). Warp per node.
// ---------------------------------------------------------------------------
__global__ __launch_bounds__(256)
void xq_kernel(const float* __restrict__ x, float* __restrict__ y, int N)
{
    __shared__ float q[256];
    if (threadIdx.x < 256) q[threadIdx.x] = g_q[threadIdx.x];
    __syncthreads();

    const int lane = threadIdx.x & 31;
    const int node = (blockIdx.x * blockDim.x + threadIdx.x) >> 5;
    if (node >= N) return;

    float a0 = 0.f, a1 = 0.f;
    const float* xr = x + (size_t)node * 128;
#pragma unroll
    for (int k = lane; k < 128; k += 32) {
        float xv = xr[k];
        a0 += xv * q[k * 2];
        a1 += xv * q[k * 2 + 1];
    }
#pragma unroll
    for (int off = 16; off; off >>= 1) {
        a0 += __shfl_xor_sync(0xffffffffu, a0, off);
        a1 += __shfl_xor_sync(0xffffffffu, a1, off);
    }
    if (lane == 0) {
        y[(size_t)node * 2] = a0;
        y[(size_t)node * 2 + 1] = a1;
    }
}

// ---------------------------------------------------------------------------
// prop2: v' = M v + s_k ; LAST applies sigmoid and writes trust output.
// ---------------------------------------------------------------------------
template <bool LAST>
__global__ __launch_bounds__(256)
void prop2_kernel(const float* __restrict__ vin, float* __restrict__ vout,
                  const float* __restrict__ dis, float* __restrict__ outp,
                  int sidx, int N)
{
    const int lane = threadIdx.x & 31;
    const int node = (blockIdx.x * blockDim.x + threadIdx.x) >> 5;
    if (node >= N) return;

    int beg = g_rowptr[node];
    int end = g_rowptr[node + 1];

    float p0 = 0.f, p1 = 0.f;
    for (int e = beg + lane; e < end; e += 32) {
        int r = g_csr_src[e];
        float wv = g_csr_norm[e];
        float2 v = *(const float2*)(vin + (size_t)r * 2);
        p0 += wv * v.x;
        p1 += wv * v.y;
    }
#pragma unroll
    for (int off = 16; off; off >>= 1) {
        p0 += __shfl_xor_sync(0xffffffffu, p0, off);
        p1 += __shfl_xor_sync(0xffffffffu, p1, off);
    }
    if (lane == 0) {
        float dd = dis[node];
        float d2 = dd * dd;
        float2 sv = *(const float2*)(vin + (size_t)node * 2);
        float r0 = p0 + d2 * sv.x + g_s[sidx][0];
        float r1 = p1 + d2 * sv.y + g_s[sidx][1];
        if (LAST) {
            outp[(size_t)node * 2]     = 1.f / (1.f + expf(-r0));
            outp[(size_t)node * 2 + 1] = 1.f / (1.f + expf(-r1));
        } else {
            vout[(size_t)node * 2]     = r0;
            vout[(size_t)node * 2 + 1] = r1;
        }
    }
}

// ---------------------------------------------------------------------------
// Launch
// ---------------------------------------------------------------------------
extern "C" void kernel_launch(void* const* d_in, const int* in_sizes, int n_in,
                              void* d_out, int out_size)
{
    const float* x = (const float*)d_in[0];
    const void* ei = d_in[1];
    const float* W1  = (const float*)d_in[2];
    const float* b1  = (const float*)d_in[3];
    const float* W2  = (const float*)d_in[4];
    const float* b2  = (const float*)d_in[5];
    const float* Wc  = (const float*)d_in[6];
    const float* bc  = (const float*)d_in[7];
    const float* We1 = (const float*)d_in[8];
    const float* be1 = (const float*)d_in[9];
    const float* We2 = (const float*)d_in[10];
    const float* be2 = (const float*)d_in[11];
    const float* We3 = (const float*)d_in[12];
    const float* be3 = (const float*)d_in[13];
    const float* We4 = (const float*)d_in[14];
    const float* be4 = (const float*)d_in[15];
    const float* Wt  = (const float*)d_in[16];
    const float* bt  = (const float*)d_in[17];
    float* out = (float*)d_out;

    const int N = in_sizes[0] / 128;
    const int E = in_sizes[1] / 2;
    const int nscan = (N + SCAN_BS - 1) / SCAN_BS;

    float *dis, *z, *y, *y2;
    __nv_bfloat16 *whi, *wlo, *pDhi, *pDlo, *pAhi, *pAlo;
    cudaGetSymbolAddress((void**)&dis, g_dis);
    cudaGetSymbolAddress((void**)&z, g_z);
    cudaGetSymbolAddress((void**)&y, g_y);
    cudaGetSymbolAddress((void**)&y2, g_y2);
    cudaGetSymbolAddress((void**)&whi, g_whi);
    cudaGetSymbolAddress((void**)&wlo, g_wlo);
    cudaGetSymbolAddress((void**)&pDhi, g_pDhi);
    cudaGetSymbolAddress((void**)&pDlo, g_pDlo);
    cudaGetSymbolAddress((void**)&pAhi, g_pAhi);
    cudaGetSymbolAddress((void**)&pAlo, g_pAlo);

    cudaFuncSetAttribute(mma_gemm_kernel<2>, cudaFuncAttributeMaxDynamicSharedMemorySize, GEMM_SMEM);

    // --- preprocessing ---
    detect_dtype_kernel<<<1, 1>>>(ei, N);
    zero_kernel<<<(N + 255) / 256, 256>>>(N);
    convert_count_kernel<<<(E + 255) / 256, 256>>>(ei, E);
    scan_blocks_kernel<<<nscan, SCAN_BS>>>(N);
    scan_tops_kernel<<<1, 512>>>(nscan);
    scan_add_kernel<<<nscan, SCAN_BS>>>(N, E);
    finalize_dis_kernel<<<(N + 255) / 256, 256>>>(N);
    fill_csr_kernel<<<(E + 255) / 256, 256>>>(E);
    conv_w_kernel<<<128, 256>>>(W1);
    gwc_kernel<<<16, 256>>>(W2, Wc, b2, bc);
    enc_chain_kernel<<<1, 256>>>(We1, We2, We3, We4, Wt, be1, be2, be3, be4, bt);

    const int AGG_BLOCKS = (N + 7) / 8;
    dim3 gw((N + 127) / 128, 2);

    // --- classification branch ---
    aggx_kernel<<<AGG_BLOCKS, 256>>>(x, pDhi, pDlo, dis, N);
    mma_gemm_kernel<2><<<gw, 256, GEMM_SMEM>>>(pDhi, pDlo, whi, wlo, b1,
                                               pAhi, pAlo, N, 128, 256);
    zmma_kernel<<<(N + 127) / 128, 256>>>(pAhi, pAlo, z, N);
    prop16_kernel<<<AGG_BLOCKS, 256>>>(z, out, dis, N);

    // --- encoder branch (fully linear, collapsed) ---
    xq_kernel<<<AGG_BLOCKS, 256>>>(x, y, N);
    prop2_kernel<false><<<AGG_BLOCKS, 256>>>(y, y2, dis, nullptr, 0, N);
    prop2_kernel<false><<<AGG_BLOCKS, 256>>>(y2, y, dis, nullptr, 1, N);
    prop2_kernel<false><<<AGG_BLOCKS, 256>>>(y, y2, dis, nullptr, 2, N);
    prop2_kernel<true><<<AGG_BLOCKS, 256>>>(y2, nullptr, dis, out + (size_t)N * 16, 3, N);
}

// round 12
// speedup vs baseline: 2.4230x; 1.1565x over previous
#include <cuda_runtime.h>
#include <cuda_bf16.h>
#include <cstdint>
#include <math.h>

#define NNODES 100000
#define NEDGES 1600000
#define SCAN_BS 256
#define BKP 40
#define ARR (128 * BKP)
#define GEMM_SMEM (2 * 4 * ARR * 2)   // 81920 B

// ---------------------------------------------------------------------------
// Scratch (device globals)
// ---------------------------------------------------------------------------
__device__ float g_dis[NNODES];
__device__ __nv_bfloat16 g_pDhi[(size_t)NNODES * 128], g_pDlo[(size_t)NNODES * 128]; // aggx split
__device__ __nv_bfloat16 g_pAhi[(size_t)NNODES * 256], g_pAlo[(size_t)NNODES * 256]; // r split
__device__ float g_z[(size_t)NNODES * 16];
__device__ float g_y[(size_t)NNODES * 2];
__device__ float g_y2[(size_t)NNODES * 2];
__device__ int   g_rows[NEDGES];
__device__ int   g_cols[NEDGES];
__device__ int   g_cnt[NNODES];
__device__ int   g_cur[NNODES];
__device__ int   g_rowptr[NNODES + 1];
__device__ int   g_btot[(NNODES + SCAN_BS - 1) / SCAN_BS + 1];
__device__ int   g_boff[(NNODES + SCAN_BS - 1) / SCAN_BS + 1];
__device__ int   g_csr_src[NEDGES];
__device__ float g_csr_norm[NEDGES];
__device__ int   g_is64;
__device__ __nv_bfloat16 g_whi[32768], g_wlo[32768];       // W1 [n][k] split
__device__ __nv_bfloat16 g_Ghi[4096], g_Glo[4096];          // G=W2Wc [j][k] split
__device__ float g_c0[16];
__device__ float g_q[256];        // q[k*2+j]
__device__ float g_s[4][2];

// ---------------------------------------------------------------------------
// Preprocessing
// ---------------------------------------------------------------------------
__global__ void init_kernel(const void* ei_raw, int N) {
    int i = blockIdx.x * blockDim.x + threadIdx.x;
    if (i < N) { g_cnt[i] = 0; g_cur[i] = 0; }
    if (i == 0) {
        const long long* p = (const long long*)ei_raw;
        int ok = 1;
        for (int k = 0; k < 8; k++) {
            long long v = p[k];
            if (v < 0 || v >= (long long)N) ok = 0;
        }
        g_is64 = ok;
    }
}

__global__ void convert_count_kernel(const void* ei_raw, int E) {
    int e = blockIdx.x * blockDim.x + threadIdx.x;
    if (e >= E) return;
    int r, c;
    if (g_is64) {
        const long long* p = (const long long*)ei_raw;
        r = (int)p[e];
        c = (int)p[(size_t)E + e];
    } else {
        const int* p = (const int*)ei_raw;
        r = p[e];
        c = p[E + e];
    }
    g_rows[e] = r;
    g_cols[e] = c;
    atomicAdd(&g_cnt[c], 1);
}

__global__ void scan_blocks_kernel(int N) {
    __shared__ int s[SCAN_BS];
    int i = blockIdx.x * SCAN_BS + threadIdx.x;
    int v = (i < N) ? g_cnt[i] : 0;
    s[threadIdx.x] = v;
    __syncthreads();
    for (int off = 1; off < SCAN_BS; off <<= 1) {
        int t = (threadIdx.x >= off) ? s[threadIdx.x - off] : 0;
        __syncthreads();
        s[threadIdx.x] += t;
        __syncthreads();
    }
    if (i < N) g_rowptr[i] = s[threadIdx.x] - v;
    if (threadIdx.x == SCAN_BS - 1) g_btot[blockIdx.x] = s[SCAN_BS - 1];
}

__global__ void scan_tops_kernel(int nblocks) {
    __shared__ int s[512];
    int v = (threadIdx.x < nblocks) ? g_btot[threadIdx.x] : 0;
    s[threadIdx.x] = v;
    __syncthreads();
    for (int off = 1; off < 512; off <<= 1) {
        int t = (threadIdx.x >= off) ? s[threadIdx.x - off] : 0;
        __syncthreads();
        s[threadIdx.x] += t;
        __syncthreads();
    }
    if (threadIdx.x < nblocks) g_boff[threadIdx.x] = s[threadIdx.x] - v;
}

__global__ void scan_add_fin_kernel(int N, int E) {
    int i = blockIdx.x * SCAN_BS + threadIdx.x;
    if (i < N) {
        g_rowptr[i] += g_boff[blockIdx.x];
        g_dis[i] = rsqrtf((float)g_cnt[i] + 1.0f);
    }
    if (i == 0) g_rowptr[N] = E;
}

__global__ void fill_csr_kernel(int E) {
    int e = blockIdx.x * blockDim.x + threadIdx.x;
    if (e >= E) return;
    int r = g_rows[e];
    int c = g_cols[e];
    int pos = g_rowptr[c] + atomicAdd(&g_cur[c], 1);
    g_csr_src[pos] = r;
    g_csr_norm[pos] = g_dis[r] * g_dis[c];
}

// W1 [K=128][F=256] fp32 -> whi/wlo [F][K] bf16
__global__ void conv_w_kernel(const float* __restrict__ W) {
    int idx = blockIdx.x * blockDim.x + threadIdx.x;
    if (idx >= 128 * 256) return;
    int k = idx / 256;
    int n = idx % 256;
    float wv = W[idx];
    __nv_bfloat16 h = __float2bfloat16(wv);
    g_whi[n * 128 + k] = h;
    g_wlo[n * 128 + k] = __float2bfloat16(wv - __bfloat162float(h));
}

// G = W2 @ Wc (256x16) -> split [j][k]; c0 = b2ᵀWc + bc
__global__ void gwc_kernel(const float* __restrict__ W2, const float* __restrict__ Wc,
                           const float* __restrict__ b2, const float* __restrict__ bc) {
    int j = blockIdx.x;
    int m = threadIdx.x;
    float s = 0.f;
    for (int k = 0; k < 128; k++) s += W2[m * 128 + k] * Wc[k * 16 + j];
    __nv_bfloat16 h = __float2bfloat16(s);
    g_Ghi[j * 256 + m] = h;
    g_Glo[j * 256 + m] = __float2bfloat16(s - __bfloat162float(h));
    if (m == 0) {
        float c = 0.f;
        for (int k = 0; k < 128; k++) c += b2[k] * Wc[k * 16 + j];
        g_c0[j] = c + bc[j];
    }
}

// Encoder weight chain
__global__ void enc_chain_kernel(const float* We1, const float* We2, const float* We3,
                                 const float* We4, const float* Wt,
                                 const float* be1, const float* be2, const float* be3,
                                 const float* be4, const float* bt) {
    __shared__ float a[256], b[256];
    int tid = threadIdx.x;
    int row = tid >> 1, j = tid & 1;
    float s;

    s = 0.f;
    for (int k = 0; k < 128; k++) s += We4[row * 128 + k] * Wt[k * 2 + j];
    a[tid] = s;
    __syncthreads();

    if (tid < 2) {
        float acc = 0.f;
        for (int k = 0; k < 128; k++) acc += be3[k] * a[k * 2 + tid];
        g_s[2][tid] = acc;
        float a4 = 0.f;
        for (int k = 0; k < 128; k++) a4 += be4[k] * Wt[k * 2 + tid];
        g_s[3][tid] = a4 + bt[tid];
    }
    s = 0.f;
    for (int k = 0; k < 128; k++) s += We3[row * 128 + k] * a[k * 2 + j];
    b[tid] = s;
    __syncthreads();

    if (tid < 2) {
        float acc = 0.f;
        for (int k = 0; k < 128; k++) acc += be2[k] * b[k * 2 + tid];
        g_s[1][tid] = acc;
    }
    s = 0.f;
    for (int k = 0; k < 128; k++) s += We2[row * 128 + k] * b[k * 2 + j];
    __syncthreads();
    a[tid] = s;
    __syncthreads();

    if (tid < 2) {
        float acc = 0.f;
        for (int k = 0; k < 128; k++) acc += be1[k] * a[k * 2 + tid];
        g_s[0][tid] = acc;
    }
    s = 0.f;
    for (int k = 0; k < 128; k++) s += We1[row * 128 + k] * a[k * 2 + j];
    g_q[tid] = s;
}

// ---------------------------------------------------------------------------
// PTX helpers
// ---------------------------------------------------------------------------
__device__ __forceinline__ void mma16816(float* d, const uint32_t* a, const uint32_t* b) {
    asm volatile("mma.sync.aligned.m16n8k16.row.col.f32.bf16.bf16.f32 "
        "{%0,%1,%2,%3}, {%4,%5,%6,%7}, {%8,%9}, {%0,%1,%2,%3};"
        : "+f"(d[0]), "+f"(d[1]), "+f"(d[2]), "+f"(d[3])
        : "r"(a[0]), "r"(a[1]), "r"(a[2]), "r"(a[3]), "r"(b[0]), "r"(b[1]));
}
__device__ __forceinline__ void ldsm4(uint32_t* r, uint32_t addr) {
    asm volatile("ldmatrix.sync.aligned.m8n8.x4.shared.b16 {%0,%1,%2,%3}, [%4];"
        : "=r"(r[0]), "=r"(r[1]), "=r"(r[2]), "=r"(r[3]) : "r"(addr));
}
__device__ __forceinline__ void cpa16(uint32_t dst, const __nv_bfloat16* src, int bytes) {
    asm volatile("cp.async.cg.shared.global [%0], [%1], 16, %2;"
                 :: "r"(dst), "l"(src), "r"(bytes));
}

// ---------------------------------------------------------------------------
// Main GEMM (128x128 tile, bf16 hi/lo 3-pass, cp.async 2-stage)
// O = split(relu(D + bias))
// ---------------------------------------------------------------------------
__global__ __launch_bounds__(256, 2)
void mma_gemm_kernel(const __nv_bfloat16* __restrict__ Ahi_g,
                     const __nv_bfloat16* __restrict__ Alo_g,
                     const __nv_bfloat16* __restrict__ whi,
                     const __nv_bfloat16* __restrict__ wlo,
                     const float* __restrict__ bias,
                     __nv_bfloat16* __restrict__ Ohi, __nv_bfloat16* __restrict__ Olo,
                     int N, int K, int F)
{
    extern __shared__ __nv_bfloat16 sm[];
    const uint32_t smBase = (uint32_t)__cvta_generic_to_shared(sm);

    const int tid = threadIdx.x;
    const int lane = tid & 31;
    const int w = tid >> 5;
    const int wm = w >> 1;
    const int wn = w & 1;
    const int m0 = blockIdx.x * 128;
    const int n0 = blockIdx.y * 128;

    const int crow = tid >> 1;
    const int cseg = (tid & 1) * 16;
    const int arow = m0 + crow;
    const int aval = (arow < N) ? 16 : 0;
    const int arowc = (arow < N) ? arow : 0;
    const __nv_bfloat16* aHi = Ahi_g + (size_t)arowc * K;
    const __nv_bfloat16* aLo = Alo_g + (size_t)arowc * K;
    const __nv_bfloat16* bHi = whi + (size_t)(n0 + crow) * K;
    const __nv_bfloat16* bLo = wlo + (size_t)(n0 + crow) * K;

#define LOAD_STAGE(st, k0) do {                                                  \
    uint32_t b_ = smBase + (uint32_t)(st) * (4 * ARR * 2);                       \
    uint32_t dA = b_ + (uint32_t)(crow * BKP + cseg) * 2;                        \
    cpa16(dA,                aHi + (k0) + cseg,     aval);                       \
    cpa16(dA + 16,           aHi + (k0) + cseg + 8, aval);                       \
    cpa16(dA + ARR * 2,      aLo + (k0) + cseg,     aval);                       \
    cpa16(dA + ARR * 2 + 16, aLo + (k0) + cseg + 8, aval);                       \
    cpa16(dA + 2 * ARR * 2,      bHi + (k0) + cseg,     16);                     \
    cpa16(dA + 2 * ARR * 2 + 16, bHi + (k0) + cseg + 8, 16);                     \
    cpa16(dA + 3 * ARR * 2,      bLo + (k0) + cseg,     16);                     \
    cpa16(dA + 3 * ARR * 2 + 16, bLo + (k0) + cseg + 8, 16);                     \
    asm volatile("cp.async.commit_group;");                                      \
} while (0)

    const int t  = lane >> 3;
    const int tr = lane & 7;
    const int a_row_l = wm * 32 + (t & 1) * 8 + tr;
    const int a_koff  = (t >> 1) * 8;
    const int b_row_l = wn * 64 + (t >> 1) * 8 + tr;
    const int b_koff  = (t & 1) * 8;

    float acc[2][8][4];
#pragma unroll
    for (int mi = 0; mi < 2; mi++)
#pragma unroll
        for (int nf = 0; nf < 8; nf++)
#pragma unroll
            for (int c = 0; c < 4; c++) acc[mi][nf][c] = 0.f;

    const int nch = K >> 5;
    LOAD_STAGE(0, 0);

    for (int ch = 0; ch < nch; ch++) {
        if (ch + 1 < nch) {
            LOAD_STAGE((ch + 1) & 1, (ch + 1) << 5);
            asm volatile("cp.async.wait_group 1;");
        } else {
            asm volatile("cp.async.wait_group 0;");
        }
        __syncthreads();

        const uint32_t sb = smBase + (uint32_t)(ch & 1) * (4 * ARR * 2);
        const uint32_t aAhi = sb;
        const uint32_t aAlo = sb + ARR * 2;
        const uint32_t aBhi = sb + 2 * ARR * 2;
        const uint32_t aBlo = sb + 3 * ARR * 2;

#pragma unroll
        for (int s = 0; s < 2; s++) {
            const int kb = s * 16;
            uint32_t ahi[2][4], alo[2][4];
#pragma unroll
            for (int mi = 0; mi < 2; mi++) {
                uint32_t off = (uint32_t)(((a_row_l + mi * 16) * BKP + kb + a_koff) * 2);
                ldsm4(ahi[mi], aAhi + off);
                ldsm4(alo[mi], aAlo + off);
            }
            uint32_t bhi[8][2], blo[8][2];
#pragma unroll
            for (int q = 0; q < 4; q++) {
                uint32_t off = (uint32_t)(((b_row_l + q * 16) * BKP + kb + b_koff) * 2);
                uint32_t r4[4];
                ldsm4(r4, aBhi + off);
                bhi[2 * q][0] = r4[0]; bhi[2 * q][1] = r4[1];
                bhi[2 * q + 1][0] = r4[2]; bhi[2 * q + 1][1] = r4[3];
                ldsm4(r4, aBlo + off);
                blo[2 * q][0] = r4[0]; blo[2 * q][1] = r4[1];
                blo[2 * q + 1][0] = r4[2]; blo[2 * q + 1][1] = r4[3];
            }
#pragma unroll
            for (int mi = 0; mi < 2; mi++)
#pragma unroll
                for (int nf = 0; nf < 8; nf++) {
                    mma16816(acc[mi][nf], ahi[mi], bhi[nf]);
                    mma16816(acc[mi][nf], ahi[mi], blo[nf]);
                    mma16816(acc[mi][nf], alo[mi], bhi[nf]);
                }
        }
        __syncthreads();
    }
#undef LOAD_STAGE

    const int crow0 = m0 + wm * 32 + (lane >> 2);
    const int ccol0 = n0 + wn * 64 + (lane & 3) * 2;
#pragma unroll
    for (int mi = 0; mi < 2; mi++) {
        int r1 = crow0 + mi * 16;
        int r2 = r1 + 8;
#pragma unroll
        for (int nf = 0; nf < 8; nf++) {
            int col = ccol0 + nf * 8;
            float b0 = bias[col], b1 = bias[col + 1];
#pragma unroll
            for (int half = 0; half < 2; half++) {
                int row = half ? r2 : r1;
                if (row >= N) continue;
                float sx = fmaxf(acc[mi][nf][half * 2 + 0] + b0, 0.f);
                float sy = fmaxf(acc[mi][nf][half * 2 + 1] + b1, 0.f);
                size_t o = (size_t)row * F + col;
                __nv_bfloat16 hx = __float2bfloat16(sx), hy = __float2bfloat16(sy);
                float lxf = sx - __bfloat162float(hx), lyf = sy - __bfloat162float(hy);
                __nv_bfloat162 th = __nv_bfloat162(hx, hy);
                __nv_bfloat162 tl = __nv_bfloat162(__float2bfloat16(lxf), __float2bfloat16(lyf));
                *(uint32_t*)(Ohi + o) = *(uint32_t*)&th;
                *(uint32_t*)(Olo + o) = *(uint32_t*)&tl;
            }
        }
    }
}

// ---------------------------------------------------------------------------
// Skinny tensor GEMM: z = r(N x 256) @ G(256 x 16), fp32 out.
// ---------------------------------------------------------------------------
__global__ __launch_bounds__(256)
void zmma_kernel(const __nv_bfloat16* __restrict__ rhi,
                 const __nv_bfloat16* __restrict__ rlo,
                 float* __restrict__ z, int N)
{
    __shared__ __nv_bfloat16 sAhi[128 * BKP];
    __shared__ __nv_bfloat16 sAlo[128 * BKP];
    __shared__ __nv_bfloat16 sBhi[16 * 264];
    __shared__ __nv_bfloat16 sBlo[16 * 264];

    const int tid = threadIdx.x;
    const int lane = tid & 31;
    const int w = tid >> 5;
    const int m0 = blockIdx.x * 128;

    const uint32_t aAhi = (uint32_t)__cvta_generic_to_shared(sAhi);
    const uint32_t aAlo = (uint32_t)__cvta_generic_to_shared(sAlo);
    const uint32_t aBhi = (uint32_t)__cvta_generic_to_shared(sBhi);
    const uint32_t aBlo = (uint32_t)__cvta_generic_to_shared(sBlo);

    for (int i = tid; i < 16 * 256; i += 256) {
        int n = i >> 8, k = i & 255;
        sBhi[n * 264 + k] = g_Ghi[i];
        sBlo[n * 264 + k] = g_Glo[i];
    }

    const int t  = lane >> 3;
    const int tr = lane & 7;
    const int a_row_l = w * 16 + (t & 1) * 8 + tr;
    const int a_koff  = (t >> 1) * 8;
    const int b_row_l = (t >> 1) * 8 + tr;
    const int b_koff  = (t & 1) * 8;

    const int crow = tid >> 1;
    const int cseg = (tid & 1) * 16;
    const int arow = m0 + crow;

    float acc[2][4];
#pragma unroll
    for (int nf = 0; nf < 2; nf++)
#pragma unroll
        for (int c = 0; c < 4; c++) acc[nf][c] = 0.f;

    for (int ch = 0; ch < 8; ch++) {
        const int k0 = ch * 32;
        uint4 vh = make_uint4(0, 0, 0, 0), vl = vh, vh2 = vh, vl2 = vh;
        if (arow < N) {
            const __nv_bfloat16* ph = rhi + (size_t)arow * 256 + k0 + cseg;
            const __nv_bfloat16* pl = rlo + (size_t)arow * 256 + k0 + cseg;
            vh = *(const uint4*)ph;  vh2 = *(const uint4*)(ph + 8);
            vl = *(const uint4*)pl;  vl2 = *(const uint4*)(pl + 8);
        }
        __syncthreads();
        *(uint4*)&sAhi[crow * BKP + cseg] = vh;
        *(uint4*)&sAhi[crow * BKP + cseg + 8] = vh2;
        *(uint4*)&sAlo[crow * BKP + cseg] = vl;
        *(uint4*)&sAlo[crow * BKP + cseg + 8] = vl2;
        __syncthreads();

#pragma unroll
        for (int s = 0; s < 2; s++) {
            const int kb = s * 16;
            uint32_t ahi[4], alo[4];
            uint32_t offA = (uint32_t)((a_row_l * BKP + kb + a_koff) * 2);
            ldsm4(ahi, aAhi + offA);
            ldsm4(alo, aAlo + offA);
            uint32_t bhi[2][2], blo[2][2];
            uint32_t offB = (uint32_t)((b_row_l * 264 + k0 + kb + b_koff) * 2);
            uint32_t r4[4];
            ldsm4(r4, aBhi + offB);
            bhi[0][0] = r4[0]; bhi[0][1] = r4[1];
            bhi[1][0] = r4[2]; bhi[1][1] = r4[3];
            ldsm4(r4, aBlo + offB);
            blo[0][0] = r4[0]; blo[0][1] = r4[1];
            blo[1][0] = r4[2]; blo[1][1] = r4[3];
#pragma unroll
            for (int nf = 0; nf < 2; nf++) {
                mma16816(acc[nf], ahi, bhi[nf]);
                mma16816(acc[nf], ahi, blo[nf]);
                mma16816(acc[nf], alo, bhi[nf]);
            }
        }
    }

    const int crow0 = m0 + w * 16 + (lane >> 2);
    const int ccol0 = (lane & 3) * 2;
#pragma unroll
    for (int nf = 0; nf < 2; nf++) {
        int col = ccol0 + nf * 8;
#pragma unroll
        for (int half = 0; half < 2; half++) {
            int row = crow0 + half * 8;
            if (row < N) {
                size_t o = (size_t)row * 16 + col;
                z[o]     = acc[nf][half * 2 + 0];
                z[o + 1] = acc[nf][half * 2 + 1];
            }
        }
    }
}

// ---------------------------------------------------------------------------
// aggx + xq fused: split(M x) and y = x[node]ᵀ q   (warp per node)
// ---------------------------------------------------------------------------
__global__ __launch_bounds__(256)
void aggx_xq_kernel(const float* __restrict__ x,
                    __nv_bfloat16* __restrict__ Ohi, __nv_bfloat16* __restrict__ Olo,
                    float* __restrict__ y,
                    const float* __restrict__ dis, int N)
{
    __shared__ float qsh[256];
    if (threadIdx.x < 256) qsh[threadIdx.x] = g_q[threadIdx.x];
    __syncthreads();

    const int lane = threadIdx.x & 31;
    const int node = (blockIdx.x * blockDim.x + threadIdx.x) >> 5;
    if (node >= N) return;

    int beg = g_rowptr[node];
    int end = g_rowptr[node + 1];

    float4 acc = make_float4(0.f, 0.f, 0.f, 0.f);
    for (int base = beg; base < end; base += 32) {
        int n = min(32, end - base);
        int srcReg = 0; float nrReg = 0.f;
        if (lane < n) {
            srcReg = g_csr_src[base + lane];
            nrReg  = g_csr_norm[base + lane];
        }
        for (int k = 0; k < n; k++) {
            int   r = __shfl_sync(0xffffffffu, srcReg, k);
            float wv = __shfl_sync(0xffffffffu, nrReg, k);
            float4 v = ((const float4*)(x + (size_t)r * 128))[lane];
            acc.x += wv * v.x; acc.y += wv * v.y;
            acc.z += wv * v.z; acc.w += wv * v.w;
        }
    }
    float dd = dis[node];
    float d2 = dd * dd;
    float4 sv = ((const float4*)(x + (size_t)node * 128))[lane];
    acc.x += d2 * sv.x; acc.y += d2 * sv.y;
    acc.z += d2 * sv.z; acc.w += d2 * sv.w;

    // xq: y = x[node] . q (2 cols), x row distributed as sv across lanes
    {
        int k4 = lane * 4;
        float a0 = sv.x * qsh[(k4 + 0) * 2] + sv.y * qsh[(k4 + 1) * 2]
                 + sv.z * qsh[(k4 + 2) * 2] + sv.w * qsh[(k4 + 3) * 2];
        float a1 = sv.x * qsh[(k4 + 0) * 2 + 1] + sv.y * qsh[(k4 + 1) * 2 + 1]
                 + sv.z * qsh[(k4 + 2) * 2 + 1] + sv.w * qsh[(k4 + 3) * 2 + 1];
#pragma unroll
        for (int off = 16; off; off >>= 1) {
            a0 += __shfl_xor_sync(0xffffffffu, a0, off);
            a1 += __shfl_xor_sync(0xffffffffu, a1, off);
        }
        if (lane == 0) {
            y[(size_t)node * 2] = a0;
            y[(size_t)node * 2 + 1] = a1;
        }
    }

    size_t o = (size_t)node * 128 + lane * 4;
    __nv_bfloat16 h0 = __float2bfloat16(acc.x), h1 = __float2bfloat16(acc.y);
    __nv_bfloat16 h2 = __float2bfloat16(acc.z), h3 = __float2bfloat16(acc.w);
    __nv_bfloat162 t01 = __nv_bfloat162(h0, h1), t23 = __nv_bfloat162(h2, h3);
    __nv_bfloat162 l01 = __nv_bfloat162(__float2bfloat16(acc.x - __bfloat162float(h0)),
                                        __float2bfloat16(acc.y - __bfloat162float(h1)));
    __nv_bfloat162 l23 = __nv_bfloat162(__float2bfloat16(acc.z - __bfloat162float(h2)),
                                        __float2bfloat16(acc.w - __bfloat162float(h3)));
    uint2 ph, pl;
    ph.x = *(uint32_t*)&t01; ph.y = *(uint32_t*)&t23;
    pl.x = *(uint32_t*)&l01; pl.y = *(uint32_t*)&l23;
    *(uint2*)(Ohi + o) = ph;
    *(uint2*)(Olo + o) = pl;
}

// ---------------------------------------------------------------------------
// prop16: out = M z + c0
// ---------------------------------------------------------------------------
__global__ __launch_bounds__(256)
void prop16_kernel(const float* __restrict__ z, float* __restrict__ outp,
                   const float* __restrict__ dis, int N)
{
    const int lane = threadIdx.x & 31;
    const int node = (blockIdx.x * blockDim.x + threadIdx.x) >> 5;
    if (node >= N) return;

    int beg = g_rowptr[node];
    int end = g_rowptr[node + 1];
    int hw = lane >> 4, f = lane & 15;

    float acc = 0.f;
    for (int e = beg + hw; e < end; e += 2) {
        int r = g_csr_src[e];
        float wv = g_csr_norm[e];
        acc += wv * z[(size_t)r * 16 + f];
    }
    acc += __shfl_xor_sync(0xffffffffu, acc, 16);
    if (hw == 0) {
        float dd = dis[node];
        outp[(size_t)node * 16 + f] = acc + dd * dd * z[(size_t)node * 16 + f] + g_c0[f];
    }
}

// ---------------------------------------------------------------------------
// prop2: v' = M v + s_k ; LAST applies sigmoid
// ---------------------------------------------------------------------------
template <bool LAST>
__global__ __launch_bounds__(256)
void prop2_kernel(const float* __restrict__ vin, float* __restrict__ vout,
                  const float* __restrict__ dis, float* __restrict__ outp,
                  int sidx, int N)
{
    const int lane = threadIdx.x & 31;
    const int node = (blockIdx.x * blockDim.x + threadIdx.x) >> 5;
    if (node >= N) return;

    int beg = g_rowptr[node];
    int end = g_rowptr[node + 1];

    float p0 = 0.f, p1 = 0.f;
    for (int e = beg + lane; e < end; e += 32) {
        int r = g_csr_src[e];
        float wv = g_csr_norm[e];
        float2 v = *(const float2*)(vin + (size_t)r * 2);
        p0 += wv * v.x;
        p1 += wv * v.y;
    }
#pragma unroll
    for (int off = 16; off; off >>= 1) {
        p0 += __shfl_xor_sync(0xffffffffu, p0, off);
        p1 += __shfl_xor_sync(0xffffffffu, p1, off);
    }
    if (lane == 0) {
        float dd = dis[node];
        float d2 = dd * dd;
        float2 sv = *(const float2*)(vin + (size_t)node * 2);
        float r0 = p0 + d2 * sv.x + g_s[sidx][0];
        float r1 = p1 + d2 * sv.y + g_s[sidx][1];
        if (LAST) {
            outp[(size_t)node * 2]     = 1.f / (1.f + expf(-r0));
            outp[(size_t)node * 2 + 1] = 1.f / (1.f + expf(-r1));
        } else {
            vout[(size_t)node * 2]     = r0;
            vout[(size_t)node * 2 + 1] = r1;
        }
    }
}

// ---------------------------------------------------------------------------
// Launch — forked-stream capture: weight prep + encoder chain overlap the
// edge preproc + classification chain.
// ---------------------------------------------------------------------------
extern "C" void kernel_launch(void* const* d_in, const int* in_sizes, int n_in,
                              void* d_out, int out_size)
{
    const float* x = (const float*)d_in[0];
    const void* ei = d_in[1];
    const float* W1  = (const float*)d_in[2];
    const float* b1  = (const float*)d_in[3];
    const float* W2  = (const float*)d_in[4];
    const float* b2  = (const float*)d_in[5];
    const float* Wc  = (const float*)d_in[6];
    const float* bc  = (const float*)d_in[7];
    const float* We1 = (const float*)d_in[8];
    const float* be1 = (const float*)d_in[9];
    const float* We2 = (const float*)d_in[10];
    const float* be2 = (const float*)d_in[11];
    const float* We3 = (const float*)d_in[12];
    const float* be3 = (const float*)d_in[13];
    const float* We4 = (const float*)d_in[14];
    const float* be4 = (const float*)d_in[15];
    const float* Wt  = (const float*)d_in[16];
    const float* bt  = (const float*)d_in[17];
    float* out = (float*)d_out;

    const int N = in_sizes[0] / 128;
    const int E = in_sizes[1] / 2;
    const int nscan = (N + SCAN_BS - 1) / SCAN_BS;

    float *dis, *z, *y, *y2;
    __nv_bfloat16 *whi, *wlo, *pDhi, *pDlo, *pAhi, *pAlo;
    cudaGetSymbolAddress((void**)&dis, g_dis);
    cudaGetSymbolAddress((void**)&z, g_z);
    cudaGetSymbolAddress((void**)&y, g_y);
    cudaGetSymbolAddress((void**)&y2, g_y2);
    cudaGetSymbolAddress((void**)&whi, g_whi);
    cudaGetSymbolAddress((void**)&wlo, g_wlo);
    cudaGetSymbolAddress((void**)&pDhi, g_pDhi);
    cudaGetSymbolAddress((void**)&pDlo, g_pDlo);
    cudaGetSymbolAddress((void**)&pAhi, g_pAhi);
    cudaGetSymbolAddress((void**)&pAlo, g_pAlo);

    cudaFuncSetAttribute(mma_gemm_kernel, cudaFuncAttributeMaxDynamicSharedMemorySize, GEMM_SMEM);

    // One-time side stream + events (created on the first, non-captured call)
    static cudaStream_t s2 = nullptr;
    static cudaEvent_t evS = nullptr, evW = nullptr, evA = nullptr, evB = nullptr;
    if (!s2) {
        cudaStreamCreateWithFlags(&s2, cudaStreamNonBlocking);
        cudaEventCreateWithFlags(&evS, cudaEventDisableTiming);
        cudaEventCreateWithFlags(&evW, cudaEventDisableTiming);
        cudaEventCreateWithFlags(&evA, cudaEventDisableTiming);
        cudaEventCreateWithFlags(&evB, cudaEventDisableTiming);
    }

    // --- fork: weight prep on s2, edge preproc on default stream ---
    cudaEventRecord(evS, 0);
    cudaStreamWaitEvent(s2, evS, 0);
    conv_w_kernel<<<128, 256, 0, s2>>>(W1);
    gwc_kernel<<<16, 256, 0, s2>>>(W2, Wc, b2, bc);
    enc_chain_kernel<<<1, 256, 0, s2>>>(We1, We2, We3, We4, Wt, be1, be2, be3, be4, bt);
    cudaEventRecord(evW, s2);

    init_kernel<<<(N + 255) / 256, 256>>>(ei, N);
    convert_count_kernel<<<(E + 255) / 256, 256>>>(ei, E);
    scan_blocks_kernel<<<nscan, SCAN_BS>>>(N);
    scan_tops_kernel<<<1, 512>>>(nscan);
    scan_add_fin_kernel<<<nscan, SCAN_BS>>>(N, E);
    fill_csr_kernel<<<(E + 255) / 256, 256>>>(E);

    const int AGG_BLOCKS = (N + 7) / 8;
    dim3 gw((N + 127) / 128, 2);

    // aggx needs q (enc_chain) — join weight prep
    cudaStreamWaitEvent(0, evW, 0);
    aggx_xq_kernel<<<AGG_BLOCKS, 256>>>(x, pDhi, pDlo, y, dis, N);
    cudaEventRecord(evA, 0);

    // --- encoder chain on s2, overlapped with classification chain ---
    cudaStreamWaitEvent(s2, evA, 0);
    prop2_kernel<false><<<AGG_BLOCKS, 256, 0, s2>>>(y, y2, dis, nullptr, 0, N);
    prop2_kernel<false><<<AGG_BLOCKS, 256, 0, s2>>>(y2, y, dis, nullptr, 1, N);
    prop2_kernel<false><<<AGG_BLOCKS, 256, 0, s2>>>(y, y2, dis, nullptr, 2, N);
    prop2_kernel<true><<<AGG_BLOCKS, 256, 0, s2>>>(y2, nullptr, dis, out + (size_t)N * 16, 3, N);
    cudaEventRecord(evB, s2);

    // --- classification chain on default stream ---
    mma_gemm_kernel<<<gw, 256, GEMM_SMEM>>>(pDhi, pDlo, whi, wlo, b1,
                                            pAhi, pAlo, N, 128, 256);
    zmma_kernel<<<(N + 127) / 128, 256>>>(pAhi, pAlo, z, N);
    prop16_kernel<<<AGG_BLOCKS, 256>>>(z, out, dis, N);

    // join encoder branch
    cudaStreamWaitEvent(0, evB, 0);
}

// round 13
// speedup vs baseline: 2.4371x; 1.0058x over previous
#include <cuda_runtime.h>
#include <cuda_bf16.h>
#include <cstdint>
#include <math.h>

#define NNODES 100000
#define NEDGES 1600000
#define SCAN_BS 256
#define BKP 40
#define ARR (128 * BKP)
#define GEMM_SMEM (2 * 4 * ARR * 2)   // 81920 B

// ---------------------------------------------------------------------------
// Scratch (device globals)
// ---------------------------------------------------------------------------
__device__ float g_dis[NNODES];
__device__ __nv_bfloat16 g_pDhi[(size_t)NNODES * 128], g_pDlo[(size_t)NNODES * 128]; // aggx split
__device__ __nv_bfloat16 g_pAhi[(size_t)NNODES * 256], g_pAlo[(size_t)NNODES * 256]; // r split
__device__ float g_z[(size_t)NNODES * 16];
__device__ float g_y[(size_t)NNODES * 2];
__device__ float g_y2[(size_t)NNODES * 2];
__device__ int   g_rows[NEDGES];
__device__ int   g_cols[NEDGES];
__device__ int   g_cnt[NNODES];
__device__ int   g_cur[NNODES];
__device__ int   g_rowptr[NNODES + 1];
__device__ int   g_btot[(NNODES + SCAN_BS - 1) / SCAN_BS + 1];
__device__ int   g_boff[(NNODES + SCAN_BS - 1) / SCAN_BS + 1];
__device__ int   g_csr_src[NEDGES];
__device__ float g_csr_norm[NEDGES];
__device__ int   g_is64;
__device__ __nv_bfloat16 g_whi[32768], g_wlo[32768];       // W1 [n][k] split
__device__ __nv_bfloat16 g_Ghi[4096], g_Glo[4096];          // G=W2Wc [j][k] split
__device__ float g_c0[16];
__device__ float g_q[256];        // q[k*2+j]
__device__ float g_s[4][2];

// ---------------------------------------------------------------------------
// Preprocessing
// ---------------------------------------------------------------------------
__global__ void init_kernel(const void* ei_raw, int N) {
    int i = blockIdx.x * blockDim.x + threadIdx.x;
    if (i < N) { g_cnt[i] = 0; g_cur[i] = 0; }
    if (i == 0) {
        const long long* p = (const long long*)ei_raw;
        int ok = 1;
        for (int k = 0; k < 8; k++) {
            long long v = p[k];
            if (v < 0 || v >= (long long)N) ok = 0;
        }
        g_is64 = ok;
    }
}

__global__ void convert_count_kernel(const void* ei_raw, int E) {
    int e = blockIdx.x * blockDim.x + threadIdx.x;
    if (e >= E) return;
    int r, c;
    if (g_is64) {
        const long long* p = (const long long*)ei_raw;
        r = (int)p[e];
        c = (int)p[(size_t)E + e];
    } else {
        const int* p = (const int*)ei_raw;
        r = p[e];
        c = p[E + e];
    }
    g_rows[e] = r;
    g_cols[e] = c;
    atomicAdd(&g_cnt[c], 1);
}

__global__ void scan_blocks_kernel(int N) {
    __shared__ int s[SCAN_BS];
    int i = blockIdx.x * SCAN_BS + threadIdx.x;
    int v = (i < N) ? g_cnt[i] : 0;
    s[threadIdx.x] = v;
    __syncthreads();
    for (int off = 1; off < SCAN_BS; off <<= 1) {
        int t = (threadIdx.x >= off) ? s[threadIdx.x - off] : 0;
        __syncthreads();
        s[threadIdx.x] += t;
        __syncthreads();
    }
    if (i < N) g_rowptr[i] = s[threadIdx.x] - v;
    if (threadIdx.x == SCAN_BS - 1) g_btot[blockIdx.x] = s[SCAN_BS - 1];
}

__global__ void scan_tops_kernel(int nblocks) {
    __shared__ int s[512];
    int v = (threadIdx.x < nblocks) ? g_btot[threadIdx.x] : 0;
    s[threadIdx.x] = v;
    __syncthreads();
    for (int off = 1; off < 512; off <<= 1) {
        int t = (threadIdx.x >= off) ? s[threadIdx.x - off] : 0;
        __syncthreads();
        s[threadIdx.x] += t;
        __syncthreads();
    }
    if (threadIdx.x < nblocks) g_boff[threadIdx.x] = s[threadIdx.x] - v;
}

__global__ void scan_add_fin_kernel(int N, int E) {
    int i = blockIdx.x * SCAN_BS + threadIdx.x;
    if (i < N) {
        g_rowptr[i] += g_boff[blockIdx.x];
        g_dis[i] = rsqrtf((float)g_cnt[i] + 1.0f);
    }
    if (i == 0) g_rowptr[N] = E;
}

__global__ void fill_csr_kernel(int E) {
    int e = blockIdx.x * blockDim.x + threadIdx.x;
    if (e >= E) return;
    int r = g_rows[e];
    int c = g_cols[e];
    int pos = g_rowptr[c] + atomicAdd(&g_cur[c], 1);
    g_csr_src[pos] = r;
    g_csr_norm[pos] = g_dis[r] * g_dis[c];
}

// W1 [K=128][F=256] fp32 -> whi/wlo [F][K] bf16
__global__ void conv_w_kernel(const float* __restrict__ W) {
    int idx = blockIdx.x * blockDim.x + threadIdx.x;
    if (idx >= 128 * 256) return;
    int k = idx / 256;
    int n = idx % 256;
    float wv = W[idx];
    __nv_bfloat16 h = __float2bfloat16(wv);
    g_whi[n * 128 + k] = h;
    g_wlo[n * 128 + k] = __float2bfloat16(wv - __bfloat162float(h));
}

// G = W2 @ Wc (256x16) -> split [j][k]; c0 = b2ᵀWc + bc
__global__ void gwc_kernel(const float* __restrict__ W2, const float* __restrict__ Wc,
                           const float* __restrict__ b2, const float* __restrict__ bc) {
    int j = blockIdx.x;
    int m = threadIdx.x;
    float s = 0.f;
    for (int k = 0; k < 128; k++) s += W2[m * 128 + k] * Wc[k * 16 + j];
    __nv_bfloat16 h = __float2bfloat16(s);
    g_Ghi[j * 256 + m] = h;
    g_Glo[j * 256 + m] = __float2bfloat16(s - __bfloat162float(h));
    if (m == 0) {
        float c = 0.f;
        for (int k = 0; k < 128; k++) c += b2[k] * Wc[k * 16 + j];
        g_c0[j] = c + bc[j];
    }
}

// Encoder weight chain
__global__ void enc_chain_kernel(const float* We1, const float* We2, const float* We3,
                                 const float* We4, const float* Wt,
                                 const float* be1, const float* be2, const float* be3,
                                 const float* be4, const float* bt) {
    __shared__ float a[256], b[256];
    int tid = threadIdx.x;
    int row = tid >> 1, j = tid & 1;
    float s;

    s = 0.f;
    for (int k = 0; k < 128; k++) s += We4[row * 128 + k] * Wt[k * 2 + j];
    a[tid] = s;
    __syncthreads();

    if (tid < 2) {
        float acc = 0.f;
        for (int k = 0; k < 128; k++) acc += be3[k] * a[k * 2 + tid];
        g_s[2][tid] = acc;
        float a4 = 0.f;
        for (int k = 0; k < 128; k++) a4 += be4[k] * Wt[k * 2 + tid];
        g_s[3][tid] = a4 + bt[tid];
    }
    s = 0.f;
    for (int k = 0; k < 128; k++) s += We3[row * 128 + k] * a[k * 2 + j];
    b[tid] = s;
    __syncthreads();

    if (tid < 2) {
        float acc = 0.f;
        for (int k = 0; k < 128; k++) acc += be2[k] * b[k * 2 + tid];
        g_s[1][tid] = acc;
    }
    s = 0.f;
    for (int k = 0; k < 128; k++) s += We2[row * 128 + k] * b[k * 2 + j];
    __syncthreads();
    a[tid] = s;
    __syncthreads();

    if (tid < 2) {
        float acc = 0.f;
        for (int k = 0; k < 128; k++) acc += be1[k] * a[k * 2 + tid];
        g_s[0][tid] = acc;
    }
    s = 0.f;
    for (int k = 0; k < 128; k++) s += We1[row * 128 + k] * a[k * 2 + j];
    g_q[tid] = s;
}

// ---------------------------------------------------------------------------
// PTX helpers
// ---------------------------------------------------------------------------
__device__ __forceinline__ void mma16816(float* d, const uint32_t* a, const uint32_t* b) {
    asm volatile("mma.sync.aligned.m16n8k16.row.col.f32.bf16.bf16.f32 "
        "{%0,%1,%2,%3}, {%4,%5,%6,%7}, {%8,%9}, {%0,%1,%2,%3};"
        : "+f"(d[0]), "+f"(d[1]), "+f"(d[2]), "+f"(d[3])
        : "r"(a[0]), "r"(a[1]), "r"(a[2]), "r"(a[3]), "r"(b[0]), "r"(b[1]));
}
__device__ __forceinline__ void ldsm4(uint32_t* r, uint32_t addr) {
    asm volatile("ldmatrix.sync.aligned.m8n8.x4.shared.b16 {%0,%1,%2,%3}, [%4];"
        : "=r"(r[0]), "=r"(r[1]), "=r"(r[2]), "=r"(r[3]) : "r"(addr));
}
__device__ __forceinline__ void cpa16(uint32_t dst, const __nv_bfloat16* src, int bytes) {
    asm volatile("cp.async.cg.shared.global [%0], [%1], 16, %2;"
                 :: "r"(dst), "l"(src), "r"(bytes));
}

// ---------------------------------------------------------------------------
// Main GEMM (128x128 tile, bf16 hi/lo 3-pass, cp.async 2-stage)
// O = split(relu(D + bias))
// ---------------------------------------------------------------------------
__global__ __launch_bounds__(256, 2)
void mma_gemm_kernel(const __nv_bfloat16* __restrict__ Ahi_g,
                     const __nv_bfloat16* __restrict__ Alo_g,
                     const __nv_bfloat16* __restrict__ whi,
                     const __nv_bfloat16* __restrict__ wlo,
                     const float* __restrict__ bias,
                     __nv_bfloat16* __restrict__ Ohi, __nv_bfloat16* __restrict__ Olo,
                     int N, int K, int F)
{
    extern __shared__ __nv_bfloat16 sm[];
    const uint32_t smBase = (uint32_t)__cvta_generic_to_shared(sm);

    const int tid = threadIdx.x;
    const int lane = tid & 31;
    const int w = tid >> 5;
    const int wm = w >> 1;
    const int wn = w & 1;
    const int m0 = blockIdx.x * 128;
    const int n0 = blockIdx.y * 128;

    const int crow = tid >> 1;
    const int cseg = (tid & 1) * 16;
    const int arow = m0 + crow;
    const int aval = (arow < N) ? 16 : 0;
    const int arowc = (arow < N) ? arow : 0;
    const __nv_bfloat16* aHi = Ahi_g + (size_t)arowc * K;
    const __nv_bfloat16* aLo = Alo_g + (size_t)arowc * K;
    const __nv_bfloat16* bHi = whi + (size_t)(n0 + crow) * K;
    const __nv_bfloat16* bLo = wlo + (size_t)(n0 + crow) * K;

#define LOAD_STAGE(st, k0) do {                                                  \
    uint32_t b_ = smBase + (uint32_t)(st) * (4 * ARR * 2);                       \
    uint32_t dA = b_ + (uint32_t)(crow * BKP + cseg) * 2;                        \
    cpa16(dA,                aHi + (k0) + cseg,     aval);                       \
    cpa16(dA + 16,           aHi + (k0) + cseg + 8, aval);                       \
    cpa16(dA + ARR * 2,      aLo + (k0) + cseg,     aval);                       \
    cpa16(dA + ARR * 2 + 16, aLo + (k0) + cseg + 8, aval);                       \
    cpa16(dA + 2 * ARR * 2,      bHi + (k0) + cseg,     16);                     \
    cpa16(dA + 2 * ARR * 2 + 16, bHi + (k0) + cseg + 8, 16);                     \
    cpa16(dA + 3 * ARR * 2,      bLo + (k0) + cseg,     16);                     \
    cpa16(dA + 3 * ARR * 2 + 16, bLo + (k0) + cseg + 8, 16);                     \
    asm volatile("cp.async.commit_group;");                                      \
} while (0)

    const int t  = lane >> 3;
    const int tr = lane & 7;
    const int a_row_l = wm * 32 + (t & 1) * 8 + tr;
    const int a_koff  = (t >> 1) * 8;
    const int b_row_l = wn * 64 + (t >> 1) * 8 + tr;
    const int b_koff  = (t & 1) * 8;

    float acc[2][8][4];
#pragma unroll
    for (int mi = 0; mi < 2; mi++)
#pragma unroll
        for (int nf = 0; nf < 8; nf++)
#pragma unroll
            for (int c = 0; c < 4; c++) acc[mi][nf][c] = 0.f;

    const int nch = K >> 5;
    LOAD_STAGE(0, 0);

    for (int ch = 0; ch < nch; ch++) {
        if (ch + 1 < nch) {
            LOAD_STAGE((ch + 1) & 1, (ch + 1) << 5);
            asm volatile("cp.async.wait_group 1;");
        } else {
            asm volatile("cp.async.wait_group 0;");
        }
        __syncthreads();

        const uint32_t sb = smBase + (uint32_t)(ch & 1) * (4 * ARR * 2);
        const uint32_t aAhi = sb;
        const uint32_t aAlo = sb + ARR * 2;
        const uint32_t aBhi = sb + 2 * ARR * 2;
        const uint32_t aBlo = sb + 3 * ARR * 2;

#pragma unroll
        for (int s = 0; s < 2; s++) {
            const int kb = s * 16;
            uint32_t ahi[2][4], alo[2][4];
#pragma unroll
            for (int mi = 0; mi < 2; mi++) {
                uint32_t off = (uint32_t)(((a_row_l + mi * 16) * BKP + kb + a_koff) * 2);
                ldsm4(ahi[mi], aAhi + off);
                ldsm4(alo[mi], aAlo + off);
            }
            uint32_t bhi[8][2], blo[8][2];
#pragma unroll
            for (int q = 0; q < 4; q++) {
                uint32_t off = (uint32_t)(((b_row_l + q * 16) * BKP + kb + b_koff) * 2);
                uint32_t r4[4];
                ldsm4(r4, aBhi + off);
                bhi[2 * q][0] = r4[0]; bhi[2 * q][1] = r4[1];
                bhi[2 * q + 1][0] = r4[2]; bhi[2 * q + 1][1] = r4[3];
                ldsm4(r4, aBlo + off);
                blo[2 * q][0] = r4[0]; blo[2 * q][1] = r4[1];
                blo[2 * q + 1][0] = r4[2]; blo[2 * q + 1][1] = r4[3];
            }
#pragma unroll
            for (int mi = 0; mi < 2; mi++)
#pragma unroll
                for (int nf = 0; nf < 8; nf++) {
                    mma16816(acc[mi][nf], ahi[mi], bhi[nf]);
                    mma16816(acc[mi][nf], ahi[mi], blo[nf]);
                    mma16816(acc[mi][nf], alo[mi], bhi[nf]);
                }
        }
        __syncthreads();
    }
#undef LOAD_STAGE

    const int crow0 = m0 + wm * 32 + (lane >> 2);
    const int ccol0 = n0 + wn * 64 + (lane & 3) * 2;
#pragma unroll
    for (int mi = 0; mi < 2; mi++) {
        int r1 = crow0 + mi * 16;
        int r2 = r1 + 8;
#pragma unroll
        for (int nf = 0; nf < 8; nf++) {
            int col = ccol0 + nf * 8;
            float b0 = bias[col], b1 = bias[col + 1];
#pragma unroll
            for (int half = 0; half < 2; half++) {
                int row = half ? r2 : r1;
                if (row >= N) continue;
                float sx = fmaxf(acc[mi][nf][half * 2 + 0] + b0, 0.f);
                float sy = fmaxf(acc[mi][nf][half * 2 + 1] + b1, 0.f);
                size_t o = (size_t)row * F + col;
                __nv_bfloat16 hx = __float2bfloat16(sx), hy = __float2bfloat16(sy);
                float lxf = sx - __bfloat162float(hx), lyf = sy - __bfloat162float(hy);
                __nv_bfloat162 th = __nv_bfloat162(hx, hy);
                __nv_bfloat162 tl = __nv_bfloat162(__float2bfloat16(lxf), __float2bfloat16(lyf));
                *(uint32_t*)(Ohi + o) = *(uint32_t*)&th;
                *(uint32_t*)(Olo + o) = *(uint32_t*)&tl;
            }
        }
    }
}

// ---------------------------------------------------------------------------
// Skinny tensor GEMM: z = r(N x 256) @ G(256 x 16), fp32 out.
// ---------------------------------------------------------------------------
__global__ __launch_bounds__(256)
void zmma_kernel(const __nv_bfloat16* __restrict__ rhi,
                 const __nv_bfloat16* __restrict__ rlo,
                 float* __restrict__ z, int N)
{
    __shared__ __nv_bfloat16 sAhi[128 * BKP];
    __shared__ __nv_bfloat16 sAlo[128 * BKP];
    __shared__ __nv_bfloat16 sBhi[16 * 264];
    __shared__ __nv_bfloat16 sBlo[16 * 264];

    const int tid = threadIdx.x;
    const int lane = tid & 31;
    const int w = tid >> 5;
    const int m0 = blockIdx.x * 128;

    const uint32_t aAhi = (uint32_t)__cvta_generic_to_shared(sAhi);
    const uint32_t aAlo = (uint32_t)__cvta_generic_to_shared(sAlo);
    const uint32_t aBhi = (uint32_t)__cvta_generic_to_shared(sBhi);
    const uint32_t aBlo = (uint32_t)__cvta_generic_to_shared(sBlo);

    for (int i = tid; i < 16 * 256; i += 256) {
        int n = i >> 8, k = i & 255;
        sBhi[n * 264 + k] = g_Ghi[i];
        sBlo[n * 264 + k] = g_Glo[i];
    }

    const int t  = lane >> 3;
    const int tr = lane & 7;
    const int a_row_l = w * 16 + (t & 1) * 8 + tr;
    const int a_koff  = (t >> 1) * 8;
    const int b_row_l = (t >> 1) * 8 + tr;
    const int b_koff  = (t & 1) * 8;

    const int crow = tid >> 1;
    const int cseg = (tid & 1) * 16;
    const int arow = m0 + crow;

    float acc[2][4];
#pragma unroll
    for (int nf = 0; nf < 2; nf++)
#pragma unroll
        for (int c = 0; c < 4; c++) acc[nf][c] = 0.f;

    for (int ch = 0; ch < 8; ch++) {
        const int k0 = ch * 32;
        uint4 vh = make_uint4(0, 0, 0, 0), vl = vh, vh2 = vh, vl2 = vh;
        if (arow < N) {
            const __nv_bfloat16* ph = rhi + (size_t)arow * 256 + k0 + cseg;
            const __nv_bfloat16* pl = rlo + (size_t)arow * 256 + k0 + cseg;
            vh = *(const uint4*)ph;  vh2 = *(const uint4*)(ph + 8);
            vl = *(const uint4*)pl;  vl2 = *(const uint4*)(pl + 8);
        }
        __syncthreads();
        *(uint4*)&sAhi[crow * BKP + cseg] = vh;
        *(uint4*)&sAhi[crow * BKP + cseg + 8] = vh2;
        *(uint4*)&sAlo[crow * BKP + cseg] = vl;
        *(uint4*)&sAlo[crow * BKP + cseg + 8] = vl2;
        __syncthreads();

#pragma unroll
        for (int s = 0; s < 2; s++) {
            const int kb = s * 16;
            uint32_t ahi[4], alo[4];
            uint32_t offA = (uint32_t)((a_row_l * BKP + kb + a_koff) * 2);
            ldsm4(ahi, aAhi + offA);
            ldsm4(alo, aAlo + offA);
            uint32_t bhi[2][2], blo[2][2];
            uint32_t offB = (uint32_t)((b_row_l * 264 + k0 + kb + b_koff) * 2);
            uint32_t r4[4];
            ldsm4(r4, aBhi + offB);
            bhi[0][0] = r4[0]; bhi[0][1] = r4[1];
            bhi[1][0] = r4[2]; bhi[1][1] = r4[3];
            ldsm4(r4, aBlo + offB);
            blo[0][0] = r4[0]; blo[0][1] = r4[1];
            blo[1][0] = r4[2]; blo[1][1] = r4[3];
#pragma unroll
            for (int nf = 0; nf < 2; nf++) {
                mma16816(acc[nf], ahi, bhi[nf]);
                mma16816(acc[nf], ahi, blo[nf]);
                mma16816(acc[nf], alo, bhi[nf]);
            }
        }
    }

    const int crow0 = m0 + w * 16 + (lane >> 2);
    const int ccol0 = (lane & 3) * 2;
#pragma unroll
    for (int nf = 0; nf < 2; nf++) {
        int col = ccol0 + nf * 8;
#pragma unroll
        for (int half = 0; half < 2; half++) {
            int row = crow0 + half * 8;
            if (row < N) {
                size_t o = (size_t)row * 16 + col;
                z[o]     = acc[nf][half * 2 + 0];
                z[o + 1] = acc[nf][half * 2 + 1];
            }
        }
    }
}

// ---------------------------------------------------------------------------
// aggx + xq fused: split(M x) and y = x[node]ᵀ q   (warp per node)
// ---------------------------------------------------------------------------
__global__ __launch_bounds__(256)
void aggx_xq_kernel(const float* __restrict__ x,
                    __nv_bfloat16* __restrict__ Ohi, __nv_bfloat16* __restrict__ Olo,
                    float* __restrict__ y,
                    const float* __restrict__ dis, int N)
{
    __shared__ float qsh[256];
    if (threadIdx.x < 256) qsh[threadIdx.x] = g_q[threadIdx.x];
    __syncthreads();

    const int lane = threadIdx.x & 31;
    const int node = (blockIdx.x * blockDim.x + threadIdx.x) >> 5;
    if (node >= N) return;

    int beg = g_rowptr[node];
    int end = g_rowptr[node + 1];

    float4 acc = make_float4(0.f, 0.f, 0.f, 0.f);
    for (int base = beg; base < end; base += 32) {
        int n = min(32, end - base);
        int srcReg = 0; float nrReg = 0.f;
        if (lane < n) {
            srcReg = g_csr_src[base + lane];
            nrReg  = g_csr_norm[base + lane];
        }
        for (int k = 0; k < n; k++) {
            int   r = __shfl_sync(0xffffffffu, srcReg, k);
            float wv = __shfl_sync(0xffffffffu, nrReg, k);
            float4 v = ((const float4*)(x + (size_t)r * 128))[lane];
            acc.x += wv * v.x; acc.y += wv * v.y;
            acc.z += wv * v.z; acc.w += wv * v.w;
        }
    }
    float dd = dis[node];
    float d2 = dd * dd;
    float4 sv = ((const float4*)(x + (size_t)node * 128))[lane];
    acc.x += d2 * sv.x; acc.y += d2 * sv.y;
    acc.z += d2 * sv.z; acc.w += d2 * sv.w;

    // xq: y = x[node] . q (2 cols), x row distributed as sv across lanes
    {
        int k4 = lane * 4;
        float a0 = sv.x * qsh[(k4 + 0) * 2] + sv.y * qsh[(k4 + 1) * 2]
                 + sv.z * qsh[(k4 + 2) * 2] + sv.w * qsh[(k4 + 3) * 2];
        float a1 = sv.x * qsh[(k4 + 0) * 2 + 1] + sv.y * qsh[(k4 + 1) * 2 + 1]
                 + sv.z * qsh[(k4 + 2) * 2 + 1] + sv.w * qsh[(k4 + 3) * 2 + 1];
#pragma unroll
        for (int off = 16; off; off >>= 1) {
            a0 += __shfl_xor_sync(0xffffffffu, a0, off);
            a1 += __shfl_xor_sync(0xffffffffu, a1, off);
        }
        if (lane == 0) {
            y[(size_t)node * 2] = a0;
            y[(size_t)node * 2 + 1] = a1;
        }
    }

    size_t o = (size_t)node * 128 + lane * 4;
    __nv_bfloat16 h0 = __float2bfloat16(acc.x), h1 = __float2bfloat16(acc.y);
    __nv_bfloat16 h2 = __float2bfloat16(acc.z), h3 = __float2bfloat16(acc.w);
    __nv_bfloat162 t01 = __nv_bfloat162(h0, h1), t23 = __nv_bfloat162(h2, h3);
    __nv_bfloat162 l01 = __nv_bfloat162(__float2bfloat16(acc.x - __bfloat162float(h0)),
                                        __float2bfloat16(acc.y - __bfloat162float(h1)));
    __nv_bfloat162 l23 = __nv_bfloat162(__float2bfloat16(acc.z - __bfloat162float(h2)),
                                        __float2bfloat16(acc.w - __bfloat162float(h3)));
    uint2 ph, pl;
    ph.x = *(uint32_t*)&t01; ph.y = *(uint32_t*)&t23;
    pl.x = *(uint32_t*)&l01; pl.y = *(uint32_t*)&l23;
    *(uint2*)(Ohi + o) = ph;
    *(uint2*)(Olo + o) = pl;
}

// ---------------------------------------------------------------------------
// prop16: out = M z + c0
// ---------------------------------------------------------------------------
__global__ __launch_bounds__(256)
void prop16_kernel(const float* __restrict__ z, float* __restrict__ outp,
                   const float* __restrict__ dis, int N)
{
    const int lane = threadIdx.x & 31;
    const int node = (blockIdx.x * blockDim.x + threadIdx.x) >> 5;
    if (node >= N) return;

    int beg = g_rowptr[node];
    int end = g_rowptr[node + 1];
    int hw = lane >> 4, f = lane & 15;

    float acc = 0.f;
    for (int e = beg + hw; e < end; e += 2) {
        int r = g_csr_src[e];
        float wv = g_csr_norm[e];
        acc += wv * z[(size_t)r * 16 + f];
    }
    acc += __shfl_xor_sync(0xffffffffu, acc, 16);
    if (hw == 0) {
        float dd = dis[node];
        outp[(size_t)node * 16 + f] = acc + dd * dd * z[(size_t)node * 16 + f] + g_c0[f];
    }
}

// ---------------------------------------------------------------------------
// prop2: v' = M v + s_k ; LAST applies sigmoid
// ---------------------------------------------------------------------------
template <bool LAST>
__global__ __launch_bounds__(256)
void prop2_kernel(const float* __restrict__ vin, float* __restrict__ vout,
                  const float* __restrict__ dis, float* __restrict__ outp,
                  int sidx, int N)
{
    const int lane = threadIdx.x & 31;
    const int node = (blockIdx.x * blockDim.x + threadIdx.x) >> 5;
    if (node >= N) return;

    int beg = g_rowptr[node];
    int end = g_rowptr[node + 1];

    float p0 = 0.f, p1 = 0.f;
    for (int e = beg + lane; e < end; e += 32) {
        int r = g_csr_src[e];
        float wv = g_csr_norm[e];
        float2 v = *(const float2*)(vin + (size_t)r * 2);
        p0 += wv * v.x;
        p1 += wv * v.y;
    }
#pragma unroll
    for (int off = 16; off; off >>= 1) {
        p0 += __shfl_xor_sync(0xffffffffu, p0, off);
        p1 += __shfl_xor_sync(0xffffffffu, p1, off);
    }
    if (lane == 0) {
        float dd = dis[node];
        float d2 = dd * dd;
        float2 sv = *(const float2*)(vin + (size_t)node * 2);
        float r0 = p0 + d2 * sv.x + g_s[sidx][0];
        float r1 = p1 + d2 * sv.y + g_s[sidx][1];
        if (LAST) {
            outp[(size_t)node * 2]     = 1.f / (1.f + expf(-r0));
            outp[(size_t)node * 2 + 1] = 1.f / (1.f + expf(-r1));
        } else {
            vout[(size_t)node * 2]     = r0;
            vout[(size_t)node * 2 + 1] = r1;
        }
    }
}

// ---------------------------------------------------------------------------
// Launch — forked-stream capture: weight prep + encoder chain overlap the
// edge preproc + classification chain.
// ---------------------------------------------------------------------------
extern "C" void kernel_launch(void* const* d_in, const int* in_sizes, int n_in,
                              void* d_out, int out_size)
{
    const float* x = (const float*)d_in[0];
    const void* ei = d_in[1];
    const float* W1  = (const float*)d_in[2];
    const float* b1  = (const float*)d_in[3];
    const float* W2  = (const float*)d_in[4];
    const float* b2  = (const float*)d_in[5];
    const float* Wc  = (const float*)d_in[6];
    const float* bc  = (const float*)d_in[7];
    const float* We1 = (const float*)d_in[8];
    const float* be1 = (const float*)d_in[9];
    const float* We2 = (const float*)d_in[10];
    const float* be2 = (const float*)d_in[11];
    const float* We3 = (const float*)d_in[12];
    const float* be3 = (const float*)d_in[13];
    const float* We4 = (const float*)d_in[14];
    const float* be4 = (const float*)d_in[15];
    const float* Wt  = (const float*)d_in[16];
    const float* bt  = (const float*)d_in[17];
    float* out = (float*)d_out;

    const int N = in_sizes[0] / 128;
    const int E = in_sizes[1] / 2;
    const int nscan = (N + SCAN_BS - 1) / SCAN_BS;

    float *dis, *z, *y, *y2;
    __nv_bfloat16 *whi, *wlo, *pDhi, *pDlo, *pAhi, *pAlo;
    cudaGetSymbolAddress((void**)&dis, g_dis);
    cudaGetSymbolAddress((void**)&z, g_z);
    cudaGetSymbolAddress((void**)&y, g_y);
    cudaGetSymbolAddress((void**)&y2, g_y2);
    cudaGetSymbolAddress((void**)&whi, g_whi);
    cudaGetSymbolAddress((void**)&wlo, g_wlo);
    cudaGetSymbolAddress((void**)&pDhi, g_pDhi);
    cudaGetSymbolAddress((void**)&pDlo, g_pDlo);
    cudaGetSymbolAddress((void**)&pAhi, g_pAhi);
    cudaGetSymbolAddress((void**)&pAlo, g_pAlo);

    cudaFuncSetAttribute(mma_gemm_kernel, cudaFuncAttributeMaxDynamicSharedMemorySize, GEMM_SMEM);

    // One-time side stream + events (created on the first, non-captured call)
    static cudaStream_t s2 = nullptr;
    static cudaEvent_t evS = nullptr, evW = nullptr, evA = nullptr, evB = nullptr;
    if (!s2) {
        cudaStreamCreateWithFlags(&s2, cudaStreamNonBlocking);
        cudaEventCreateWithFlags(&evS, cudaEventDisableTiming);
        cudaEventCreateWithFlags(&evW, cudaEventDisableTiming);
        cudaEventCreateWithFlags(&evA, cudaEventDisableTiming);
        cudaEventCreateWithFlags(&evB, cudaEventDisableTiming);
    }

    // --- fork: weight prep on s2, edge preproc on default stream ---
    cudaEventRecord(evS, 0);
    cudaStreamWaitEvent(s2, evS, 0);
    conv_w_kernel<<<128, 256, 0, s2>>>(W1);
    gwc_kernel<<<16, 256, 0, s2>>>(W2, Wc, b2, bc);
    enc_chain_kernel<<<1, 256, 0, s2>>>(We1, We2, We3, We4, Wt, be1, be2, be3, be4, bt);
    cudaEventRecord(evW, s2);

    init_kernel<<<(N + 255) / 256, 256>>>(ei, N);
    convert_count_kernel<<<(E + 255) / 256, 256>>>(ei, E);
    scan_blocks_kernel<<<nscan, SCAN_BS>>>(N);
    scan_tops_kernel<<<1, 512>>>(nscan);
    scan_add_fin_kernel<<<nscan, SCAN_BS>>>(N, E);
    fill_csr_kernel<<<(E + 255) / 256, 256>>>(E);

    const int AGG_BLOCKS = (N + 7) / 8;
    dim3 gw((N + 127) / 128, 2);

    // aggx needs q (enc_chain) — join weight prep
    cudaStreamWaitEvent(0, evW, 0);
    aggx_xq_kernel<<<AGG_BLOCKS, 256>>>(x, pDhi, pDlo, y, dis, N);
    cudaEventRecord(evA, 0);

    // --- encoder chain on s2, overlapped with classification chain ---
    cudaStreamWaitEvent(s2, evA, 0);
    prop2_kernel<false><<<AGG_BLOCKS, 256, 0, s2>>>(y, y2, dis, nullptr, 0, N);
    prop2_kernel<false><<<AGG_BLOCKS, 256, 0, s2>>>(y2, y, dis, nullptr, 1, N);
    prop2_kernel<false><<<AGG_BLOCKS, 256, 0, s2>>>(y, y2, dis, nullptr, 2, N);
    prop2_kernel<true><<<AGG_BLOCKS, 256, 0, s2>>>(y2, nullptr, dis, out + (size_t)N * 16, 3, N);
    cudaEventRecord(evB, s2);

    // --- classification chain on default stream ---
    mma_gemm_kernel<<<gw, 256, GEMM_SMEM>>>(pDhi, pDlo, whi, wlo, b1,
                                            pAhi, pAlo, N, 128, 256);
    zmma_kernel<<<(N + 127) / 128, 256>>>(pAhi, pAlo, z, N);
    prop16_kernel<<<AGG_BLOCKS, 256>>>(z, out, dis, N);

    // join encoder branch
    cudaStreamWaitEvent(0, evB, 0);
}